// round 9
// baseline (speedup 1.0000x reference)
#include <cuda_runtime.h>
#include <cuda_bf16.h>
#include <math.h>
#include <stdint.h>

// Problem constants
#define B_   2
#define S_   2048
#define D_   2048
#define H_   16
#define HD_  128
#define M_   (B_ * S_)      // 4096
#define NQKV (3 * D_)       // 6144
#define K_   D_             // 2048

// ---------------- scratch (device globals) ---------------------------------
__device__ float g_qkv[(size_t)M_ * NQKV];
__device__ float g_q  [(size_t)M_ * D_];   // [b,h,s,hd], tf32-rounded
__device__ float g_k  [(size_t)M_ * D_];
__device__ float g_v  [(size_t)M_ * D_];
__device__ float g_attn[(size_t)M_ * D_];  // [b,s,h,hd], tf32-rounded
__device__ float g_wor [(size_t)D_ * D_];  // w_out tf32-rounded

__device__ __align__(1024) __nv_bfloat16 g_xh [(size_t)M_ * D_];
__device__ __align__(1024) __nv_bfloat16 g_xl [(size_t)M_ * D_];
__device__ __align__(1024) __nv_bfloat16 g_wqh[(size_t)NQKV * D_];
__device__ __align__(1024) __nv_bfloat16 g_wql[(size_t)NQKV * D_];

// ======================= PTX helpers (compute_103-safe) =====================
__device__ __forceinline__ uint32_t s2u(const void* p) {
    uint32_t a;
    asm("{ .reg .u64 t; cvta.to.shared.u64 t, %1; cvt.u32.u64 %0, t; }"
        : "=r"(a) : "l"(p));
    return a;
}
__device__ __forceinline__ void cp16(uint32_t dst, const void* src) {
    asm volatile("cp.async.ca.shared.global [%0], [%1], 16;" :: "r"(dst), "l"(src));
}
__device__ __forceinline__ void cp_commit() {
    asm volatile("cp.async.commit_group;" ::: "memory");
}
__device__ __forceinline__ void cp_wait0() {
    asm volatile("cp.async.wait_group 0;" ::: "memory");
}
__device__ __forceinline__ void cp_wait1() {
    asm volatile("cp.async.wait_group 1;" ::: "memory");
}
__device__ __forceinline__ void ldsm_x4(uint32_t* r, uint32_t addr) {
    asm volatile("ldmatrix.sync.aligned.m8n8.x4.shared.b16 {%0,%1,%2,%3}, [%4];"
                 : "=r"(r[0]), "=r"(r[1]), "=r"(r[2]), "=r"(r[3]) : "r"(addr));
}
__device__ __forceinline__ void ldsm_x2(uint32_t* r, uint32_t addr) {
    asm volatile("ldmatrix.sync.aligned.m8n8.x2.shared.b16 {%0,%1}, [%2];"
                 : "=r"(r[0]), "=r"(r[1]) : "r"(addr));
}
__device__ __forceinline__ void mma_bf16(float* d, const uint32_t* a, const uint32_t* b) {
    asm volatile(
        "mma.sync.aligned.m16n8k16.row.col.f32.bf16.bf16.f32 "
        "{%0,%1,%2,%3}, {%4,%5,%6,%7}, {%8,%9}, {%0,%1,%2,%3};"
        : "+f"(d[0]), "+f"(d[1]), "+f"(d[2]), "+f"(d[3])
        : "r"(a[0]), "r"(a[1]), "r"(a[2]), "r"(a[3]), "r"(b[0]), "r"(b[1]));
}
__device__ __forceinline__ void mma_tf32(float* d, const uint32_t* a, const uint32_t* b) {
    asm volatile(
        "mma.sync.aligned.m16n8k8.row.col.f32.tf32.tf32.f32 "
        "{%0,%1,%2,%3}, {%4,%5,%6,%7}, {%8,%9}, {%0,%1,%2,%3};"
        : "+f"(d[0]), "+f"(d[1]), "+f"(d[2]), "+f"(d[3])
        : "r"(a[0]), "r"(a[1]), "r"(a[2]), "r"(a[3]), "r"(b[0]), "r"(b[1]));
}
__device__ __forceinline__ float tf32r(float x) {
    uint32_t u;
    asm("cvt.rna.tf32.f32 %0, %1;" : "=r"(u) : "f"(x));
    return __uint_as_float(u);
}

// ======================= fp32 -> (hi, lo) bf16 split =======================
__global__ __launch_bounds__(256)
void split_f32(const float4* __restrict__ in, uint2* __restrict__ hi,
               uint2* __restrict__ lo, int n4)
{
    int i = blockIdx.x * 256 + threadIdx.x;
    if (i >= n4) return;
    float4 v = in[i];
    __nv_bfloat16 h0 = __float2bfloat16(v.x);
    __nv_bfloat16 h1 = __float2bfloat16(v.y);
    __nv_bfloat16 h2 = __float2bfloat16(v.z);
    __nv_bfloat16 h3 = __float2bfloat16(v.w);
    __nv_bfloat16 l0 = __float2bfloat16(v.x - __bfloat162float(h0));
    __nv_bfloat16 l1 = __float2bfloat16(v.y - __bfloat162float(h1));
    __nv_bfloat16 l2 = __float2bfloat16(v.z - __bfloat162float(h2));
    __nv_bfloat16 l3 = __float2bfloat16(v.w - __bfloat162float(h3));
    uint2 hp, lp;
    hp.x = (uint32_t)__bfloat16_as_ushort(h0) | ((uint32_t)__bfloat16_as_ushort(h1) << 16);
    hp.y = (uint32_t)__bfloat16_as_ushort(h2) | ((uint32_t)__bfloat16_as_ushort(h3) << 16);
    lp.x = (uint32_t)__bfloat16_as_ushort(l0) | ((uint32_t)__bfloat16_as_ushort(l1) << 16);
    lp.y = (uint32_t)__bfloat16_as_ushort(l2) | ((uint32_t)__bfloat16_as_ushort(l3) << 16);
    hi[i] = hp;
    lo[i] = lp;
}

// ======================= fp32 -> tf32(rna) round ===========================
__global__ __launch_bounds__(256)
void round_tf32(const float4* __restrict__ in, float4* __restrict__ out, int n4)
{
    int i = blockIdx.x * 256 + threadIdx.x;
    if (i >= n4) return;
    float4 v = in[i];
    float4 r = {tf32r(v.x), tf32r(v.y), tf32r(v.z), tf32r(v.w)};
    out[i] = r;
}

// ======================= split-bf16 GEMM via mma.sync ======================
// C[M,N] = A[M,K] * B[N,K]^T. 128x128 tile, BK=32, 2-stage cp.async.
// Stage layout (32KB): A tile 128 rows x [32 bf16 hi | 32 bf16 lo] = 16KB,
// then B tile same. SW128 swizzle on 128-byte rows; lo = hi byte offset + 64.
// 2 CTAs/SM (64KB smem, <=128 regs).
#define G_STAGE_BYTES  32768
#define G_SMEM_BYTES   (2 * G_STAGE_BYTES)   // 65536

__device__ __forceinline__ void g_load_stage(uint32_t sbase, const char* gA_h,
                                             const char* gA_l, const char* gB_h,
                                             const char* gB_l, int k0, int t)
{
#pragma unroll
    for (int i = 0; i < 8; ++i) {
        int c = t + i * 256;            // 0..2047
        int tile = c >> 10;             // 0=A, 1=B
        int row  = (c & 1023) >> 3;     // 0..127
        int sub  = c & 7;               // 0-3: hi 16B chunks, 4-7: lo
        const char* gh = tile ? gB_h : gA_h;
        const char* gl = tile ? gB_l : gA_l;
        const char* src = (sub < 4 ? gh : gl)
                        + (size_t)row * (K_ * 2) + (size_t)k0 * 2 + (sub & 3) * 16;
        uint32_t off = row * 128 + sub * 16;
        uint32_t sw = off ^ ((off >> 3) & 0x70);
        cp16(sbase + tile * 16384 + sw, src);
    }
    cp_commit();
}

__global__ __launch_bounds__(256, 2)
void gemm_mma(const __nv_bfloat16* __restrict__ Ah, const __nv_bfloat16* __restrict__ Al,
              const __nv_bfloat16* __restrict__ Bh, const __nv_bfloat16* __restrict__ Bl,
              float* __restrict__ C, int N)
{
    extern __shared__ __align__(1024) char smem_raw[];
    uint32_t sb = s2u(smem_raw);
    const int t    = threadIdx.x;
    const int wid  = t >> 5;
    const int lane = t & 31;
    const int g    = lane >> 2;
    const int c    = lane & 3;
    const int m0w  = (wid >> 2) * 64;
    const int n0w  = (wid & 3) * 32;
    const int rowBase = blockIdx.y << 7;
    const int colBase = blockIdx.x << 7;

    const int a_row = (lane & 7) + ((lane >> 3) & 1) * 8;
    const int a_cb  = (lane >> 4) * 16;
    const int l16   = lane & 15;
    const int b_row = l16 & 7;
    const int b_cb  = (l16 >> 3) * 16;

    float acc[4][4][4];
#pragma unroll
    for (int mb = 0; mb < 4; ++mb)
#pragma unroll
        for (int nb = 0; nb < 4; ++nb)
#pragma unroll
            for (int r = 0; r < 4; ++r) acc[mb][nb][r] = 0.f;

    const char* gA_h = (const char*)Ah + (size_t)rowBase * K_ * 2;
    const char* gA_l = (const char*)Al + (size_t)rowBase * K_ * 2;
    const char* gB_h = (const char*)Bh + (size_t)colBase * K_ * 2;
    const char* gB_l = (const char*)Bl + (size_t)colBase * K_ * 2;

    const int NT = K_ / 32;    // 64

    g_load_stage(sb, gA_h, gA_l, gB_h, gB_l, 0, t);
    cp_wait0();
    __syncthreads();

    for (int kt = 0; kt < NT; ++kt) {
        const int s = kt & 1;
        if (kt + 1 < NT)
            g_load_stage(sb + (s ^ 1) * G_STAGE_BYTES, gA_h, gA_l, gB_h, gB_l,
                         (kt + 1) << 5, t);
        const uint32_t st = sb + s * G_STAGE_BYTES;

#pragma unroll
        for (int ks = 0; ks < 2; ++ks) {
            uint32_t ah[4][4], al[4][4], bh[4][2], bl[4][2];
#pragma unroll
            for (int mb = 0; mb < 4; ++mb) {
                int row = m0w + mb * 16 + a_row;
                uint32_t offh = row * 128 + ks * 32 + a_cb;
                uint32_t offl = offh + 64;
                ldsm_x4(ah[mb], st + (offh ^ ((offh >> 3) & 0x70)));
                ldsm_x4(al[mb], st + (offl ^ ((offl >> 3) & 0x70)));
            }
#pragma unroll
            for (int nb = 0; nb < 4; ++nb) {
                int row = n0w + nb * 8 + b_row;
                uint32_t offh = row * 128 + ks * 32 + b_cb;
                uint32_t offl = offh + 64;
                ldsm_x2(bh[nb], st + 16384 + (offh ^ ((offh >> 3) & 0x70)));
                ldsm_x2(bl[nb], st + 16384 + (offl ^ ((offl >> 3) & 0x70)));
            }
#pragma unroll
            for (int mb = 0; mb < 4; ++mb)
#pragma unroll
                for (int nb = 0; nb < 4; ++nb) {
                    mma_bf16(acc[mb][nb], ah[mb], bh[nb]);
                    mma_bf16(acc[mb][nb], ah[mb], bl[nb]);
                    mma_bf16(acc[mb][nb], al[mb], bh[nb]);
                }
        }
        if (kt + 1 < NT) cp_wait0();
        __syncthreads();
    }

#pragma unroll
    for (int mb = 0; mb < 4; ++mb)
#pragma unroll
        for (int nb = 0; nb < 4; ++nb) {
            int row = rowBase + m0w + mb * 16 + g;
            int col = colBase + n0w + nb * 8 + 2 * c;
            float2 v0 = {acc[mb][nb][0], acc[mb][nb][1]};
            float2 v1 = {acc[mb][nb][2], acc[mb][nb][3]};
            *(float2*)(C + (size_t)row * N + col)       = v0;
            *(float2*)(C + (size_t)(row + 8) * N + col) = v1;
        }
}

// ======================= single-pass tf32 GEMM (GEMM2) =====================
#define T_STAGE_BYTES 32768
#define T_SMEM_BYTES  (2 * T_STAGE_BYTES)   // 65536

__device__ __forceinline__ void t_load_stage(uint32_t sbase, const float* gA,
                                             const float* gB, int k0, int t)
{
    const float* gs[2] = {gA, gB};
#pragma unroll
    for (int ts = 0; ts < 2; ++ts) {
        const float* g = gs[ts] + k0;
        uint32_t tb = sbase + ts * 16384;
#pragma unroll
        for (int i = 0; i < 4; ++i) {
            int c = t + i * 256;
            int row = c >> 3, cc = c & 7;
            uint32_t off = row * 128 + cc * 16;
            uint32_t sw = off ^ ((off >> 3) & 0x70);
            cp16(tb + sw, g + (size_t)row * K_ + cc * 4);
        }
    }
    cp_commit();
}

__global__ __launch_bounds__(256, 2)
void gemm_tf32(const float* __restrict__ A, const float* __restrict__ B,
               float* __restrict__ C, int N)
{
    extern __shared__ __align__(1024) float smf[];
    const int t    = threadIdx.x;
    const int wid  = t >> 5;
    const int lane = t & 31;
    const int g    = lane >> 2;
    const int c    = lane & 3;
    const int m0w  = (wid >> 2) * 64;
    const int n0w  = (wid & 3) * 32;
    const int rowBase = blockIdx.y << 7;
    const int colBase = blockIdx.x << 7;

    uint32_t sb = s2u(smf);

    float acc[4][4][4];
#pragma unroll
    for (int mb = 0; mb < 4; ++mb)
#pragma unroll
        for (int nb = 0; nb < 4; ++nb)
#pragma unroll
            for (int r = 0; r < 4; ++r) acc[mb][nb][r] = 0.f;

    const float* gA = A + (size_t)rowBase * K_;
    const float* gB = B + (size_t)colBase * K_;

    const int NT = K_ / 32;   // 64

    t_load_stage(sb, gA, gB, 0, t);
    cp_wait0();
    __syncthreads();

    const int gx4 = g << 2;

    for (int kt = 0; kt < NT; ++kt) {
        const int s = kt & 1;
        if (kt + 1 < NT)
            t_load_stage(sb + (s ^ 1) * T_STAGE_BYTES, gA, gB, (kt + 1) << 5, t);
        const int sA = s * 8192;
        const int sB = sA + 4096;

#pragma unroll
        for (int ks = 0; ks < 4; ++ks) {
            const int c0 = ((ks << 3) + c) ^ gx4;
            const int c1 = ((ks << 3) + c + 4) ^ gx4;
            uint32_t a[4][4], bfr[4][2];
#pragma unroll
            for (int mb = 0; mb < 4; ++mb) {
                int r0 = (m0w + mb * 16 + g) << 5;
                a[mb][0] = __float_as_uint(smf[sA + r0 + c0]);
                a[mb][1] = __float_as_uint(smf[sA + r0 + 256 + c0]);
                a[mb][2] = __float_as_uint(smf[sA + r0 + c1]);
                a[mb][3] = __float_as_uint(smf[sA + r0 + 256 + c1]);
            }
#pragma unroll
            for (int nb = 0; nb < 4; ++nb) {
                int rn = (n0w + nb * 8 + g) << 5;
                bfr[nb][0] = __float_as_uint(smf[sB + rn + c0]);
                bfr[nb][1] = __float_as_uint(smf[sB + rn + c1]);
            }
#pragma unroll
            for (int mb = 0; mb < 4; ++mb)
#pragma unroll
                for (int nb = 0; nb < 4; ++nb)
                    mma_tf32(acc[mb][nb], a[mb], bfr[nb]);
        }
        if (kt + 1 < NT) cp_wait0();
        __syncthreads();
    }

#pragma unroll
    for (int mb = 0; mb < 4; ++mb)
#pragma unroll
        for (int nb = 0; nb < 4; ++nb) {
            int row = rowBase + m0w + mb * 16 + g;
            int col = colBase + n0w + nb * 8 + 2 * c;
            float2 v0 = {acc[mb][nb][0], acc[mb][nb][1]};
            float2 v1 = {acc[mb][nb][2], acc[mb][nb][3]};
            *(float2*)(C + (size_t)row * N + col)       = v0;
            *(float2*)(C + (size_t)(row + 8) * N + col) = v1;
        }
}

// ---------------------------------------------------------------------------
// RoPE + unit-norm + q*attn_scale; tf32-rounded q/k/v in [b,h,s,hd].
// ---------------------------------------------------------------------------
__global__ __launch_bounds__(64)
void rope_norm_kernel(const float* __restrict__ qkv,
                      const float* __restrict__ freqs,
                      const float* __restrict__ scale_p,
                      float* __restrict__ gq, float* __restrict__ gk,
                      float* __restrict__ gv)
{
    const int idx = blockIdx.x;
    const int h = idx % H_;
    const int s = (idx / H_) % S_;
    const int b = idx / (H_ * S_);
    const int i = threadIdx.x;

    const float* base = qkv + (size_t)(b * S_ + s) * NQKV + h * HD_;
    float q0 = base[2 * i],           q1 = base[2 * i + 1];
    float k0 = base[D_ + 2 * i],      k1 = base[D_ + 2 * i + 1];
    float v0 = base[2 * D_ + 2 * i],  v1 = base[2 * D_ + 2 * i + 1];

    float cs = freqs[((size_t)s * 64 + i) * 2 + 0];
    float sn = freqs[((size_t)s * 64 + i) * 2 + 1];

    float qr = q0 * cs - q1 * sn, qi = q0 * sn + q1 * cs;
    float kr = k0 * cs - k1 * sn, ki = k0 * sn + k1 * cs;

    float sq = qr * qr + qi * qi;
    float sk = kr * kr + ki * ki;
#pragma unroll
    for (int off = 16; off > 0; off >>= 1) {
        sq += __shfl_xor_sync(0xffffffffu, sq, off);
        sk += __shfl_xor_sync(0xffffffffu, sk, off);
    }
    __shared__ float smq[2], smk[2];
    if ((i & 31) == 0) { smq[i >> 5] = sq; smk[i >> 5] = sk; }
    __syncthreads();
    float nq = sqrtf(smq[0] + smq[1]) + 1e-6f;
    float nk = sqrtf(smk[0] + smk[1]) + 1e-6f;

    float scl = *scale_p;
    float qs = scl / nq;
    float ks = 1.0f / nk;

    size_t o = ((size_t)(b * H_ + h) * S_ + s) * HD_;
    gq[o + 2 * i] = tf32r(qr * qs);  gq[o + 2 * i + 1] = tf32r(qi * qs);
    gk[o + 2 * i] = tf32r(kr * ks);  gk[o + 2 * i + 1] = tf32r(ki * ks);
    gv[o + 2 * i] = tf32r(v0);       gv[o + 2 * i + 1] = tf32r(v1);
}

// ---------------------------------------------------------------------------
// tf32 flash attention (R8, unchanged). BM=128, BN=64, 256 threads.
// ---------------------------------------------------------------------------
#define QS_OFF 0
#define KS_OFF (128 * 132)
#define KS_BUF (64 * 132)
#define VS_OFF (KS_OFF + 2 * KS_BUF)
#define PS_OFF (VS_OFF + 64 * 136)
#define AT_SMEM_FLOATS (PS_OFF + 128 * 68)
#define AT_SMEM_BYTES (AT_SMEM_FLOATS * 4)    // 204800

__global__ __launch_bounds__(256)
void flash_tc(const float* __restrict__ gq, const float* __restrict__ gk,
              const float* __restrict__ gv, float* __restrict__ gout)
{
    extern __shared__ float sm[];
    uint32_t smb = s2u(sm);
    const int t    = threadIdx.x;
    const int w    = t >> 5;
    const int lane = t & 31;
    const int g    = lane >> 2;
    const int c    = lane & 3;
    const int qt   = (gridDim.x - 1) - blockIdx.x;   // heavy tiles first
    const int bh   = blockIdx.y;
    const int b    = bh >> 4;
    const int h    = bh & 15;
    const int qr0  = w * 16;

    const float* Qg = gq + ((size_t)bh * S_ + qt * 128) * HD_;
    const float* Kg = gk + (size_t)bh * S_ * HD_;
    const float* Vg = gv + (size_t)bh * S_ * HD_;

#pragma unroll
    for (int i = 0; i < 16; ++i) {
        int ci = t + i * 256;
        int row = ci >> 5, cc = ci & 31;
        cp16(smb + (QS_OFF + row * 132 + cc * 4) * 4, Qg + row * HD_ + cc * 4);
    }
    cp_commit();

    const int nkv = 2 * qt + 2;

#pragma unroll
    for (int i = 0; i < 8; ++i) {
        int ci = t + i * 256;
        int row = ci >> 5, cc = ci & 31;
        cp16(smb + (KS_OFF + row * 132 + cc * 4) * 4, Kg + (size_t)row * HD_ + cc * 4);
    }
    cp_commit();
#pragma unroll
    for (int i = 0; i < 8; ++i) {
        int ci = t + i * 256;
        int row = ci >> 5, cc = ci & 31;
        cp16(smb + (VS_OFF + row * 136 + cc * 4) * 4, Vg + (size_t)row * HD_ + cc * 4);
    }
    cp_commit();

    float O[16][4];
#pragma unroll
    for (int nb = 0; nb < 16; ++nb)
#pragma unroll
        for (int r = 0; r < 4; ++r) O[nb][r] = 0.f;
    float m0 = -1e30f, m1 = -1e30f, l0 = 0.f, l1 = 0.f;

    for (int kt = 0; kt < nkv; ++kt) {
        cp_wait1();
        __syncthreads();

        if (kt + 1 < nkv) {
            const float* ksrc = Kg + (size_t)(kt + 1) * 64 * HD_;
            uint32_t kdst = smb + (KS_OFF + ((kt + 1) & 1) * KS_BUF) * 4;
#pragma unroll
            for (int i = 0; i < 8; ++i) {
                int ci = t + i * 256;
                int row = ci >> 5, cc = ci & 31;
                cp16(kdst + (row * 132 + cc * 4) * 4, ksrc + (size_t)row * HD_ + cc * 4);
            }
            cp_commit();
        }

        const int kbase = KS_OFF + (kt & 1) * KS_BUF;
        float sacc[8][4];
#pragma unroll
        for (int nb = 0; nb < 8; ++nb)
#pragma unroll
            for (int r = 0; r < 4; ++r) sacc[nb][r] = 0.f;

#pragma unroll
        for (int ks = 0; ks < 16; ++ks) {
            const int k0 = ks * 8;
            uint32_t a[4];
            a[0] = __float_as_uint(sm[QS_OFF + (qr0 + g) * 132 + k0 + c]);
            a[1] = __float_as_uint(sm[QS_OFF + (qr0 + g + 8) * 132 + k0 + c]);
            a[2] = __float_as_uint(sm[QS_OFF + (qr0 + g) * 132 + k0 + c + 4]);
            a[3] = __float_as_uint(sm[QS_OFF + (qr0 + g + 8) * 132 + k0 + c + 4]);
#pragma unroll
            for (int nb = 0; nb < 8; ++nb) {
                uint32_t bfr[2];
                bfr[0] = __float_as_uint(sm[kbase + (nb * 8 + g) * 132 + k0 + c]);
                bfr[1] = __float_as_uint(sm[kbase + (nb * 8 + g) * 132 + k0 + c + 4]);
                mma_tf32(sacc[nb], a, bfr);
            }
        }

        if (kt >= 2 * qt) {
            int rg0 = qt * 128 + qr0 + g;
#pragma unroll
            for (int nb = 0; nb < 8; ++nb) {
                int col = kt * 64 + nb * 8 + 2 * c;
                if (col     > rg0)     sacc[nb][0] = -1e30f;
                if (col + 1 > rg0)     sacc[nb][1] = -1e30f;
                if (col     > rg0 + 8) sacc[nb][2] = -1e30f;
                if (col + 1 > rg0 + 8) sacc[nb][3] = -1e30f;
            }
        }

        float rm0 = -1e30f, rm1 = -1e30f;
#pragma unroll
        for (int nb = 0; nb < 8; ++nb) {
            rm0 = fmaxf(rm0, fmaxf(sacc[nb][0], sacc[nb][1]));
            rm1 = fmaxf(rm1, fmaxf(sacc[nb][2], sacc[nb][3]));
        }
        rm0 = fmaxf(rm0, __shfl_xor_sync(0xffffffffu, rm0, 1));
        rm0 = fmaxf(rm0, __shfl_xor_sync(0xffffffffu, rm0, 2));
        rm1 = fmaxf(rm1, __shfl_xor_sync(0xffffffffu, rm1, 1));
        rm1 = fmaxf(rm1, __shfl_xor_sync(0xffffffffu, rm1, 2));
        float mn0 = fmaxf(m0, rm0), mn1 = fmaxf(m1, rm1);
        float al0 = __expf(m0 - mn0), al1 = __expf(m1 - mn1);
        float rs0 = 0.f, rs1 = 0.f;
#pragma unroll
        for (int nb = 0; nb < 8; ++nb) {
            sacc[nb][0] = __expf(sacc[nb][0] - mn0);
            sacc[nb][1] = __expf(sacc[nb][1] - mn0);
            sacc[nb][2] = __expf(sacc[nb][2] - mn1);
            sacc[nb][3] = __expf(sacc[nb][3] - mn1);
            rs0 += sacc[nb][0] + sacc[nb][1];
            rs1 += sacc[nb][2] + sacc[nb][3];
        }
        rs0 += __shfl_xor_sync(0xffffffffu, rs0, 1);
        rs0 += __shfl_xor_sync(0xffffffffu, rs0, 2);
        rs1 += __shfl_xor_sync(0xffffffffu, rs1, 1);
        rs1 += __shfl_xor_sync(0xffffffffu, rs1, 2);
        l0 = l0 * al0 + rs0;  m0 = mn0;
        l1 = l1 * al1 + rs1;  m1 = mn1;
#pragma unroll
        for (int nb = 0; nb < 16; ++nb) {
            O[nb][0] *= al0; O[nb][1] *= al0;
            O[nb][2] *= al1; O[nb][3] *= al1;
        }

#pragma unroll
        for (int nb = 0; nb < 8; ++nb) {
            int colp = nb * 8 + 2 * c;
            sm[PS_OFF + (qr0 + g) * 68 + colp]         = tf32r(sacc[nb][0]);
            sm[PS_OFF + (qr0 + g) * 68 + colp + 1]     = tf32r(sacc[nb][1]);
            sm[PS_OFF + (qr0 + g + 8) * 68 + colp]     = tf32r(sacc[nb][2]);
            sm[PS_OFF + (qr0 + g + 8) * 68 + colp + 1] = tf32r(sacc[nb][3]);
        }
        __syncwarp();

        if (kt + 1 < nkv) cp_wait1(); else cp_wait0();
        __syncthreads();

#pragma unroll
        for (int ks = 0; ks < 8; ++ks) {
            const int k0 = ks * 8;
            uint32_t a[4];
            a[0] = __float_as_uint(sm[PS_OFF + (qr0 + g) * 68 + k0 + c]);
            a[1] = __float_as_uint(sm[PS_OFF + (qr0 + g + 8) * 68 + k0 + c]);
            a[2] = __float_as_uint(sm[PS_OFF + (qr0 + g) * 68 + k0 + c + 4]);
            a[3] = __float_as_uint(sm[PS_OFF + (qr0 + g + 8) * 68 + k0 + c + 4]);
#pragma unroll
            for (int nb = 0; nb < 16; ++nb) {
                uint32_t bfr[2];
                bfr[0] = __float_as_uint(sm[VS_OFF + (k0 + c) * 136 + nb * 8 + g]);
                bfr[1] = __float_as_uint(sm[VS_OFF + (k0 + c + 4) * 136 + nb * 8 + g]);
                mma_tf32(O[nb], a, bfr);
            }
        }
        __syncthreads();

        if (kt + 1 < nkv) {
            const float* vsrc = Vg + (size_t)(kt + 1) * 64 * HD_;
#pragma unroll
            for (int i = 0; i < 8; ++i) {
                int ci = t + i * 256;
                int row = ci >> 5, cc = ci & 31;
                cp16(smb + (VS_OFF + row * 136 + cc * 4) * 4,
                     vsrc + (size_t)row * HD_ + cc * 4);
            }
            cp_commit();
        }
    }

    float inv0 = 1.f / l0, inv1 = 1.f / l1;
    int r0 = qt * 128 + qr0 + g;
    int r1 = r0 + 8;
#pragma unroll
    for (int nb = 0; nb < 16; ++nb) {
        int d = nb * 8 + 2 * c;
        float2 v0 = {tf32r(O[nb][0] * inv0), tf32r(O[nb][1] * inv0)};
        float2 v1 = {tf32r(O[nb][2] * inv1), tf32r(O[nb][3] * inv1)};
        *(float2*)(gout + ((size_t)(b * S_ + r0) * H_ + h) * HD_ + d) = v0;
        *(float2*)(gout + ((size_t)(b * S_ + r1) * H_ + h) * HD_ + d) = v1;
    }
}

// ---------------------------------------------------------------------------
extern "C" void kernel_launch(void* const* d_in, const int* in_sizes, int n_in,
                              void* d_out, int out_size)
{
    const float* x      = (const float*)d_in[0];
    const float* freqs  = (const float*)d_in[1];
    const float* wqkv   = (const float*)d_in[2];
    const float* wout   = (const float*)d_in[3];
    const float* ascale = (const float*)d_in[4];
    float* out = (float*)d_out;

    float *qkv, *q, *k, *v, *attn, *wor;
    __nv_bfloat16 *xh, *xl, *wqh, *wql;
    cudaGetSymbolAddress((void**)&qkv,  g_qkv);
    cudaGetSymbolAddress((void**)&q,    g_q);
    cudaGetSymbolAddress((void**)&k,    g_k);
    cudaGetSymbolAddress((void**)&v,    g_v);
    cudaGetSymbolAddress((void**)&attn, g_attn);
    cudaGetSymbolAddress((void**)&wor,  g_wor);
    cudaGetSymbolAddress((void**)&xh,   g_xh);
    cudaGetSymbolAddress((void**)&xl,   g_xl);
    cudaGetSymbolAddress((void**)&wqh,  g_wqh);
    cudaGetSymbolAddress((void**)&wql,  g_wql);

    cudaFuncSetAttribute(gemm_mma, cudaFuncAttributeMaxDynamicSharedMemorySize,
                         G_SMEM_BYTES);
    cudaFuncSetAttribute(gemm_tf32, cudaFuncAttributeMaxDynamicSharedMemorySize,
                         T_SMEM_BYTES);
    cudaFuncSetAttribute(flash_tc, cudaFuncAttributeMaxDynamicSharedMemorySize,
                         AT_SMEM_BYTES);

    // 0) split GEMM1 inputs; round w_out to tf32
    {
        int n4 = (M_ * D_) / 4;
        split_f32<<<(n4 + 255) / 256, 256>>>((const float4*)x, (uint2*)xh, (uint2*)xl, n4);
    }
    {
        int n4 = (NQKV * D_) / 4;
        split_f32<<<(n4 + 255) / 256, 256>>>((const float4*)wqkv, (uint2*)wqh, (uint2*)wql, n4);
    }
    {
        int n4 = (D_ * D_) / 4;
        round_tf32<<<(n4 + 255) / 256, 256>>>((const float4*)wout, (float4*)wor, n4);
    }

    // 1) qkv = x @ w_qkv^T  (split-bf16, 3-pass, 2 CTAs/SM)
    gemm_mma<<<dim3(NQKV / 128, M_ / 128), 256, G_SMEM_BYTES>>>(xh, xl, wqh, wql, qkv, NQKV);

    // 2) RoPE + norm + scale (tf32-rounded outputs)
    rope_norm_kernel<<<B_ * S_ * H_, 64>>>(qkv, freqs, ascale, q, k, v);

    // 3) flash attention -> tf32-rounded attn [b,s,h,hd]
    flash_tc<<<dim3(S_ / 128, B_ * H_), 256, AT_SMEM_BYTES>>>(q, k, v, attn);

    // 4) out = attn @ w_out^T  (single-pass tf32, 2 CTAs/SM)
    gemm_tf32<<<dim3(D_ / 128, M_ / 128), 256, T_SMEM_BYTES>>>(attn, wor, out, D_);
}

// round 10
// speedup vs baseline: 1.1544x; 1.1544x over previous
#include <cuda_runtime.h>
#include <cuda_bf16.h>
#include <math.h>
#include <stdint.h>

// Problem constants
#define B_   2
#define S_   2048
#define D_   2048
#define H_   16
#define HD_  128
#define M_   (B_ * S_)      // 4096
#define NQKV (3 * D_)       // 6144
#define K_   D_             // 2048

// ---------------- scratch (device globals) ---------------------------------
__device__ float g_qkv[(size_t)M_ * NQKV];
__device__ float g_q  [(size_t)M_ * D_];   // [b,h,s,hd], tf32-rounded
__device__ float g_k  [(size_t)M_ * D_];
__device__ float g_v  [(size_t)M_ * D_];
__device__ float g_attn[(size_t)M_ * D_];  // [b,s,h,hd], tf32-rounded
__device__ float g_wor [(size_t)D_ * D_];  // w_out  tf32-rounded
__device__ float g_xr  [(size_t)M_ * D_];  // x      tf32-rounded
__device__ float g_wqr [(size_t)NQKV * D_];// w_qkv  tf32-rounded

// ======================= PTX helpers (compute_103-safe) =====================
__device__ __forceinline__ uint32_t s2u(const void* p) {
    uint32_t a;
    asm("{ .reg .u64 t; cvta.to.shared.u64 t, %1; cvt.u32.u64 %0, t; }"
        : "=r"(a) : "l"(p));
    return a;
}
__device__ __forceinline__ void cp16(uint32_t dst, const void* src) {
    asm volatile("cp.async.ca.shared.global [%0], [%1], 16;" :: "r"(dst), "l"(src));
}
__device__ __forceinline__ void cp_commit() {
    asm volatile("cp.async.commit_group;" ::: "memory");
}
__device__ __forceinline__ void cp_wait0() {
    asm volatile("cp.async.wait_group 0;" ::: "memory");
}
__device__ __forceinline__ void cp_wait1() {
    asm volatile("cp.async.wait_group 1;" ::: "memory");
}
__device__ __forceinline__ void mma_tf32(float* d, const uint32_t* a, const uint32_t* b) {
    asm volatile(
        "mma.sync.aligned.m16n8k8.row.col.f32.tf32.tf32.f32 "
        "{%0,%1,%2,%3}, {%4,%5,%6,%7}, {%8,%9}, {%0,%1,%2,%3};"
        : "+f"(d[0]), "+f"(d[1]), "+f"(d[2]), "+f"(d[3])
        : "r"(a[0]), "r"(a[1]), "r"(a[2]), "r"(a[3]), "r"(b[0]), "r"(b[1]));
}
__device__ __forceinline__ float tf32r(float x) {
    uint32_t u;
    asm("cvt.rna.tf32.f32 %0, %1;" : "=r"(u) : "f"(x));
    return __uint_as_float(u);
}

// ======================= fp32 -> tf32(rna) round ===========================
__global__ __launch_bounds__(256)
void round_tf32(const float4* __restrict__ in, float4* __restrict__ out, int n4)
{
    int i = blockIdx.x * 256 + threadIdx.x;
    if (i >= n4) return;
    float4 v = in[i];
    float4 r = {tf32r(v.x), tf32r(v.y), tf32r(v.z), tf32r(v.w)};
    out[i] = r;
}

// ======================= single-pass tf32 GEMM =============================
// C[M,N] = A[M,K] * B[N,K]^T, A/B fp32 already tf32-rounded (RNA).
// 128x128 tile, BK=32 floats, 2-stage cp.async, swizzled fp32 smem.
#define T_STAGE_BYTES 32768
#define T_SMEM_BYTES  (2 * T_STAGE_BYTES)   // 65536

__device__ __forceinline__ void t_load_stage(uint32_t sbase, const float* gA,
                                             const float* gB, int k0, int t)
{
    const float* gs[2] = {gA, gB};
#pragma unroll
    for (int ts = 0; ts < 2; ++ts) {
        const float* g = gs[ts] + k0;
        uint32_t tb = sbase + ts * 16384;
#pragma unroll
        for (int i = 0; i < 4; ++i) {
            int c = t + i * 256;
            int row = c >> 3, cc = c & 7;
            uint32_t off = row * 128 + cc * 16;
            uint32_t sw = off ^ ((off >> 3) & 0x70);
            cp16(tb + sw, g + (size_t)row * K_ + cc * 4);
        }
    }
    cp_commit();
}

__global__ __launch_bounds__(256, 2)
void gemm_tf32(const float* __restrict__ A, const float* __restrict__ B,
               float* __restrict__ C, int N)
{
    extern __shared__ __align__(1024) float smf[];
    const int t    = threadIdx.x;
    const int wid  = t >> 5;
    const int lane = t & 31;
    const int g    = lane >> 2;
    const int c    = lane & 3;
    const int m0w  = (wid >> 2) * 64;
    const int n0w  = (wid & 3) * 32;
    const int rowBase = blockIdx.y << 7;
    const int colBase = blockIdx.x << 7;

    uint32_t sb = s2u(smf);

    float acc[4][4][4];
#pragma unroll
    for (int mb = 0; mb < 4; ++mb)
#pragma unroll
        for (int nb = 0; nb < 4; ++nb)
#pragma unroll
            for (int r = 0; r < 4; ++r) acc[mb][nb][r] = 0.f;

    const float* gA = A + (size_t)rowBase * K_;
    const float* gB = B + (size_t)colBase * K_;

    const int NT = K_ / 32;   // 64

    t_load_stage(sb, gA, gB, 0, t);
    cp_wait0();
    __syncthreads();

    const int gx4 = g << 2;

    for (int kt = 0; kt < NT; ++kt) {
        const int s = kt & 1;
        if (kt + 1 < NT)
            t_load_stage(sb + (s ^ 1) * T_STAGE_BYTES, gA, gB, (kt + 1) << 5, t);
        const int sA = s * 8192;
        const int sB = sA + 4096;

#pragma unroll
        for (int ks = 0; ks < 4; ++ks) {
            const int c0 = ((ks << 3) + c) ^ gx4;
            const int c1 = ((ks << 3) + c + 4) ^ gx4;
            uint32_t a[4][4], bfr[4][2];
#pragma unroll
            for (int mb = 0; mb < 4; ++mb) {
                int r0 = (m0w + mb * 16 + g) << 5;
                a[mb][0] = __float_as_uint(smf[sA + r0 + c0]);
                a[mb][1] = __float_as_uint(smf[sA + r0 + 256 + c0]);
                a[mb][2] = __float_as_uint(smf[sA + r0 + c1]);
                a[mb][3] = __float_as_uint(smf[sA + r0 + 256 + c1]);
            }
#pragma unroll
            for (int nb = 0; nb < 4; ++nb) {
                int rn = (n0w + nb * 8 + g) << 5;
                bfr[nb][0] = __float_as_uint(smf[sB + rn + c0]);
                bfr[nb][1] = __float_as_uint(smf[sB + rn + c1]);
            }
#pragma unroll
            for (int mb = 0; mb < 4; ++mb)
#pragma unroll
                for (int nb = 0; nb < 4; ++nb)
                    mma_tf32(acc[mb][nb], a[mb], bfr[nb]);
        }
        if (kt + 1 < NT) cp_wait0();
        __syncthreads();
    }

#pragma unroll
    for (int mb = 0; mb < 4; ++mb)
#pragma unroll
        for (int nb = 0; nb < 4; ++nb) {
            int row = rowBase + m0w + mb * 16 + g;
            int col = colBase + n0w + nb * 8 + 2 * c;
            float2 v0 = {acc[mb][nb][0], acc[mb][nb][1]};
            float2 v1 = {acc[mb][nb][2], acc[mb][nb][3]};
            *(float2*)(C + (size_t)row * N + col)       = v0;
            *(float2*)(C + (size_t)(row + 8) * N + col) = v1;
        }
}

// ---------------------------------------------------------------------------
// RoPE + unit-norm + q*attn_scale; tf32-rounded q/k/v in [b,h,s,hd].
// ---------------------------------------------------------------------------
__global__ __launch_bounds__(64)
void rope_norm_kernel(const float* __restrict__ qkv,
                      const float* __restrict__ freqs,
                      const float* __restrict__ scale_p,
                      float* __restrict__ gq, float* __restrict__ gk,
                      float* __restrict__ gv)
{
    const int idx = blockIdx.x;
    const int h = idx % H_;
    const int s = (idx / H_) % S_;
    const int b = idx / (H_ * S_);
    const int i = threadIdx.x;

    const float* base = qkv + (size_t)(b * S_ + s) * NQKV + h * HD_;
    float q0 = base[2 * i],           q1 = base[2 * i + 1];
    float k0 = base[D_ + 2 * i],      k1 = base[D_ + 2 * i + 1];
    float v0 = base[2 * D_ + 2 * i],  v1 = base[2 * D_ + 2 * i + 1];

    float cs = freqs[((size_t)s * 64 + i) * 2 + 0];
    float sn = freqs[((size_t)s * 64 + i) * 2 + 1];

    float qr = q0 * cs - q1 * sn, qi = q0 * sn + q1 * cs;
    float kr = k0 * cs - k1 * sn, ki = k0 * sn + k1 * cs;

    float sq = qr * qr + qi * qi;
    float sk = kr * kr + ki * ki;
#pragma unroll
    for (int off = 16; off > 0; off >>= 1) {
        sq += __shfl_xor_sync(0xffffffffu, sq, off);
        sk += __shfl_xor_sync(0xffffffffu, sk, off);
    }
    __shared__ float smq[2], smk[2];
    if ((i & 31) == 0) { smq[i >> 5] = sq; smk[i >> 5] = sk; }
    __syncthreads();
    float nq = sqrtf(smq[0] + smq[1]) + 1e-6f;
    float nk = sqrtf(smk[0] + smk[1]) + 1e-6f;

    float scl = *scale_p;
    float qs = scl / nq;
    float ks = 1.0f / nk;

    size_t o = ((size_t)(b * H_ + h) * S_ + s) * HD_;
    gq[o + 2 * i] = tf32r(qr * qs);  gq[o + 2 * i + 1] = tf32r(qi * qs);
    gk[o + 2 * i] = tf32r(kr * ks);  gk[o + 2 * i + 1] = tf32r(ki * ks);
    gv[o + 2 * i] = tf32r(v0);       gv[o + 2 * i + 1] = tf32r(v1);
}

// ---------------------------------------------------------------------------
// tf32 flash attention (R8, unchanged). BM=128, BN=64, 256 threads.
// ---------------------------------------------------------------------------
#define QS_OFF 0
#define KS_OFF (128 * 132)
#define KS_BUF (64 * 132)
#define VS_OFF (KS_OFF + 2 * KS_BUF)
#define PS_OFF (VS_OFF + 64 * 136)
#define AT_SMEM_FLOATS (PS_OFF + 128 * 68)
#define AT_SMEM_BYTES (AT_SMEM_FLOATS * 4)    // 204800

__global__ __launch_bounds__(256)
void flash_tc(const float* __restrict__ gq, const float* __restrict__ gk,
              const float* __restrict__ gv, float* __restrict__ gout)
{
    extern __shared__ float sm[];
    uint32_t smb = s2u(sm);
    const int t    = threadIdx.x;
    const int w    = t >> 5;
    const int lane = t & 31;
    const int g    = lane >> 2;
    const int c    = lane & 3;
    const int qt   = (gridDim.x - 1) - blockIdx.x;   // heavy tiles first
    const int bh   = blockIdx.y;
    const int b    = bh >> 4;
    const int h    = bh & 15;
    const int qr0  = w * 16;

    const float* Qg = gq + ((size_t)bh * S_ + qt * 128) * HD_;
    const float* Kg = gk + (size_t)bh * S_ * HD_;
    const float* Vg = gv + (size_t)bh * S_ * HD_;

#pragma unroll
    for (int i = 0; i < 16; ++i) {
        int ci = t + i * 256;
        int row = ci >> 5, cc = ci & 31;
        cp16(smb + (QS_OFF + row * 132 + cc * 4) * 4, Qg + row * HD_ + cc * 4);
    }
    cp_commit();

    const int nkv = 2 * qt + 2;

#pragma unroll
    for (int i = 0; i < 8; ++i) {
        int ci = t + i * 256;
        int row = ci >> 5, cc = ci & 31;
        cp16(smb + (KS_OFF + row * 132 + cc * 4) * 4, Kg + (size_t)row * HD_ + cc * 4);
    }
    cp_commit();
#pragma unroll
    for (int i = 0; i < 8; ++i) {
        int ci = t + i * 256;
        int row = ci >> 5, cc = ci & 31;
        cp16(smb + (VS_OFF + row * 136 + cc * 4) * 4, Vg + (size_t)row * HD_ + cc * 4);
    }
    cp_commit();

    float O[16][4];
#pragma unroll
    for (int nb = 0; nb < 16; ++nb)
#pragma unroll
        for (int r = 0; r < 4; ++r) O[nb][r] = 0.f;
    float m0 = -1e30f, m1 = -1e30f, l0 = 0.f, l1 = 0.f;

    for (int kt = 0; kt < nkv; ++kt) {
        cp_wait1();
        __syncthreads();

        if (kt + 1 < nkv) {
            const float* ksrc = Kg + (size_t)(kt + 1) * 64 * HD_;
            uint32_t kdst = smb + (KS_OFF + ((kt + 1) & 1) * KS_BUF) * 4;
#pragma unroll
            for (int i = 0; i < 8; ++i) {
                int ci = t + i * 256;
                int row = ci >> 5, cc = ci & 31;
                cp16(kdst + (row * 132 + cc * 4) * 4, ksrc + (size_t)row * HD_ + cc * 4);
            }
            cp_commit();
        }

        const int kbase = KS_OFF + (kt & 1) * KS_BUF;
        float sacc[8][4];
#pragma unroll
        for (int nb = 0; nb < 8; ++nb)
#pragma unroll
            for (int r = 0; r < 4; ++r) sacc[nb][r] = 0.f;

#pragma unroll
        for (int ks = 0; ks < 16; ++ks) {
            const int k0 = ks * 8;
            uint32_t a[4];
            a[0] = __float_as_uint(sm[QS_OFF + (qr0 + g) * 132 + k0 + c]);
            a[1] = __float_as_uint(sm[QS_OFF + (qr0 + g + 8) * 132 + k0 + c]);
            a[2] = __float_as_uint(sm[QS_OFF + (qr0 + g) * 132 + k0 + c + 4]);
            a[3] = __float_as_uint(sm[QS_OFF + (qr0 + g + 8) * 132 + k0 + c + 4]);
#pragma unroll
            for (int nb = 0; nb < 8; ++nb) {
                uint32_t bfr[2];
                bfr[0] = __float_as_uint(sm[kbase + (nb * 8 + g) * 132 + k0 + c]);
                bfr[1] = __float_as_uint(sm[kbase + (nb * 8 + g) * 132 + k0 + c + 4]);
                mma_tf32(sacc[nb], a, bfr);
            }
        }

        if (kt >= 2 * qt) {
            int rg0 = qt * 128 + qr0 + g;
#pragma unroll
            for (int nb = 0; nb < 8; ++nb) {
                int col = kt * 64 + nb * 8 + 2 * c;
                if (col     > rg0)     sacc[nb][0] = -1e30f;
                if (col + 1 > rg0)     sacc[nb][1] = -1e30f;
                if (col     > rg0 + 8) sacc[nb][2] = -1e30f;
                if (col + 1 > rg0 + 8) sacc[nb][3] = -1e30f;
            }
        }

        float rm0 = -1e30f, rm1 = -1e30f;
#pragma unroll
        for (int nb = 0; nb < 8; ++nb) {
            rm0 = fmaxf(rm0, fmaxf(sacc[nb][0], sacc[nb][1]));
            rm1 = fmaxf(rm1, fmaxf(sacc[nb][2], sacc[nb][3]));
        }
        rm0 = fmaxf(rm0, __shfl_xor_sync(0xffffffffu, rm0, 1));
        rm0 = fmaxf(rm0, __shfl_xor_sync(0xffffffffu, rm0, 2));
        rm1 = fmaxf(rm1, __shfl_xor_sync(0xffffffffu, rm1, 1));
        rm1 = fmaxf(rm1, __shfl_xor_sync(0xffffffffu, rm1, 2));
        float mn0 = fmaxf(m0, rm0), mn1 = fmaxf(m1, rm1);
        float al0 = __expf(m0 - mn0), al1 = __expf(m1 - mn1);
        float rs0 = 0.f, rs1 = 0.f;
#pragma unroll
        for (int nb = 0; nb < 8; ++nb) {
            sacc[nb][0] = __expf(sacc[nb][0] - mn0);
            sacc[nb][1] = __expf(sacc[nb][1] - mn0);
            sacc[nb][2] = __expf(sacc[nb][2] - mn1);
            sacc[nb][3] = __expf(sacc[nb][3] - mn1);
            rs0 += sacc[nb][0] + sacc[nb][1];
            rs1 += sacc[nb][2] + sacc[nb][3];
        }
        rs0 += __shfl_xor_sync(0xffffffffu, rs0, 1);
        rs0 += __shfl_xor_sync(0xffffffffu, rs0, 2);
        rs1 += __shfl_xor_sync(0xffffffffu, rs1, 1);
        rs1 += __shfl_xor_sync(0xffffffffu, rs1, 2);
        l0 = l0 * al0 + rs0;  m0 = mn0;
        l1 = l1 * al1 + rs1;  m1 = mn1;
#pragma unroll
        for (int nb = 0; nb < 16; ++nb) {
            O[nb][0] *= al0; O[nb][1] *= al0;
            O[nb][2] *= al1; O[nb][3] *= al1;
        }

#pragma unroll
        for (int nb = 0; nb < 8; ++nb) {
            int colp = nb * 8 + 2 * c;
            sm[PS_OFF + (qr0 + g) * 68 + colp]         = tf32r(sacc[nb][0]);
            sm[PS_OFF + (qr0 + g) * 68 + colp + 1]     = tf32r(sacc[nb][1]);
            sm[PS_OFF + (qr0 + g + 8) * 68 + colp]     = tf32r(sacc[nb][2]);
            sm[PS_OFF + (qr0 + g + 8) * 68 + colp + 1] = tf32r(sacc[nb][3]);
        }
        __syncwarp();

        if (kt + 1 < nkv) cp_wait1(); else cp_wait0();
        __syncthreads();

#pragma unroll
        for (int ks = 0; ks < 8; ++ks) {
            const int k0 = ks * 8;
            uint32_t a[4];
            a[0] = __float_as_uint(sm[PS_OFF + (qr0 + g) * 68 + k0 + c]);
            a[1] = __float_as_uint(sm[PS_OFF + (qr0 + g + 8) * 68 + k0 + c]);
            a[2] = __float_as_uint(sm[PS_OFF + (qr0 + g) * 68 + k0 + c + 4]);
            a[3] = __float_as_uint(sm[PS_OFF + (qr0 + g + 8) * 68 + k0 + c + 4]);
#pragma unroll
            for (int nb = 0; nb < 16; ++nb) {
                uint32_t bfr[2];
                bfr[0] = __float_as_uint(sm[VS_OFF + (k0 + c) * 136 + nb * 8 + g]);
                bfr[1] = __float_as_uint(sm[VS_OFF + (k0 + c + 4) * 136 + nb * 8 + g]);
                mma_tf32(O[nb], a, bfr);
            }
        }
        __syncthreads();

        if (kt + 1 < nkv) {
            const float* vsrc = Vg + (size_t)(kt + 1) * 64 * HD_;
#pragma unroll
            for (int i = 0; i < 8; ++i) {
                int ci = t + i * 256;
                int row = ci >> 5, cc = ci & 31;
                cp16(smb + (VS_OFF + row * 136 + cc * 4) * 4,
                     vsrc + (size_t)row * HD_ + cc * 4);
            }
            cp_commit();
        }
    }

    float inv0 = 1.f / l0, inv1 = 1.f / l1;
    int r0 = qt * 128 + qr0 + g;
    int r1 = r0 + 8;
#pragma unroll
    for (int nb = 0; nb < 16; ++nb) {
        int d = nb * 8 + 2 * c;
        float2 v0 = {tf32r(O[nb][0] * inv0), tf32r(O[nb][1] * inv0)};
        float2 v1 = {tf32r(O[nb][2] * inv1), tf32r(O[nb][3] * inv1)};
        *(float2*)(gout + ((size_t)(b * S_ + r0) * H_ + h) * HD_ + d) = v0;
        *(float2*)(gout + ((size_t)(b * S_ + r1) * H_ + h) * HD_ + d) = v1;
    }
}

// ---------------------------------------------------------------------------
extern "C" void kernel_launch(void* const* d_in, const int* in_sizes, int n_in,
                              void* d_out, int out_size)
{
    const float* x      = (const float*)d_in[0];
    const float* freqs  = (const float*)d_in[1];
    const float* wqkv   = (const float*)d_in[2];
    const float* wout   = (const float*)d_in[3];
    const float* ascale = (const float*)d_in[4];
    float* out = (float*)d_out;

    float *qkv, *q, *k, *v, *attn, *wor, *xr, *wqr;
    cudaGetSymbolAddress((void**)&qkv,  g_qkv);
    cudaGetSymbolAddress((void**)&q,    g_q);
    cudaGetSymbolAddress((void**)&k,    g_k);
    cudaGetSymbolAddress((void**)&v,    g_v);
    cudaGetSymbolAddress((void**)&attn, g_attn);
    cudaGetSymbolAddress((void**)&wor,  g_wor);
    cudaGetSymbolAddress((void**)&xr,   g_xr);
    cudaGetSymbolAddress((void**)&wqr,  g_wqr);

    cudaFuncSetAttribute(gemm_tf32, cudaFuncAttributeMaxDynamicSharedMemorySize,
                         T_SMEM_BYTES);
    cudaFuncSetAttribute(flash_tc, cudaFuncAttributeMaxDynamicSharedMemorySize,
                         AT_SMEM_BYTES);

    // 0) tf32(RNA) pre-round all GEMM operands
    {
        int n4 = (M_ * D_) / 4;
        round_tf32<<<(n4 + 255) / 256, 256>>>((const float4*)x, (float4*)xr, n4);
    }
    {
        int n4 = (NQKV * D_) / 4;
        round_tf32<<<(n4 + 255) / 256, 256>>>((const float4*)wqkv, (float4*)wqr, n4);
    }
    {
        int n4 = (D_ * D_) / 4;
        round_tf32<<<(n4 + 255) / 256, 256>>>((const float4*)wout, (float4*)wor, n4);
    }

    // 1) qkv = x @ w_qkv^T  (single-pass tf32)
    gemm_tf32<<<dim3(NQKV / 128, M_ / 128), 256, T_SMEM_BYTES>>>(xr, wqr, qkv, NQKV);

    // 2) RoPE + norm + scale (tf32-rounded outputs)
    rope_norm_kernel<<<B_ * S_ * H_, 64>>>(qkv, freqs, ascale, q, k, v);

    // 3) flash attention -> tf32-rounded attn [b,s,h,hd]
    flash_tc<<<dim3(S_ / 128, B_ * H_), 256, AT_SMEM_BYTES>>>(q, k, v, attn);

    // 4) out = attn @ w_out^T  (single-pass tf32)
    gemm_tf32<<<dim3(D_ / 128, M_ / 128), 256, T_SMEM_BYTES>>>(attn, wor, out, D_);
}

// round 11
// speedup vs baseline: 1.2559x; 1.0880x over previous
#include <cuda_runtime.h>
#include <cuda_bf16.h>
#include <math.h>
#include <stdint.h>

// Problem constants
#define B_   2
#define S_   2048
#define D_   2048
#define H_   16
#define HD_  128
#define M_   (B_ * S_)      // 4096
#define NQKV (3 * D_)       // 6144
#define K_   D_             // 2048

// ---------------- scratch (device globals) ---------------------------------
__device__ float g_qkv[(size_t)M_ * NQKV];
__device__ float g_q  [(size_t)M_ * D_];   // [b,h,s,hd], tf32-rounded
__device__ float g_k  [(size_t)M_ * D_];
__device__ float g_v  [(size_t)M_ * D_];
__device__ float g_attn[(size_t)M_ * D_];  // [b,s,h,hd], tf32-rounded
__device__ float g_wor [(size_t)D_ * D_];  // w_out  tf32-rounded
__device__ float g_xr  [(size_t)M_ * D_];  // x      tf32-rounded
__device__ float g_wqr [(size_t)NQKV * D_];// w_qkv  tf32-rounded

// ======================= PTX helpers (compute_103-safe) =====================
__device__ __forceinline__ uint32_t s2u(const void* p) {
    uint32_t a;
    asm("{ .reg .u64 t; cvta.to.shared.u64 t, %1; cvt.u32.u64 %0, t; }"
        : "=r"(a) : "l"(p));
    return a;
}
__device__ __forceinline__ void cp16(uint32_t dst, const void* src) {
    asm volatile("cp.async.ca.shared.global [%0], [%1], 16;" :: "r"(dst), "l"(src));
}
__device__ __forceinline__ void cp_commit() {
    asm volatile("cp.async.commit_group;" ::: "memory");
}
__device__ __forceinline__ void cp_wait0() {
    asm volatile("cp.async.wait_group 0;" ::: "memory");
}
__device__ __forceinline__ void cp_wait1() {
    asm volatile("cp.async.wait_group 1;" ::: "memory");
}
__device__ __forceinline__ void ldsm_x4(uint32_t* r, uint32_t addr) {
    asm volatile("ldmatrix.sync.aligned.m8n8.x4.shared.b16 {%0,%1,%2,%3}, [%4];"
                 : "=r"(r[0]), "=r"(r[1]), "=r"(r[2]), "=r"(r[3]) : "r"(addr));
}
__device__ __forceinline__ void mma_tf32(float* d, const uint32_t* a, const uint32_t* b) {
    asm volatile(
        "mma.sync.aligned.m16n8k8.row.col.f32.tf32.tf32.f32 "
        "{%0,%1,%2,%3}, {%4,%5,%6,%7}, {%8,%9}, {%0,%1,%2,%3};"
        : "+f"(d[0]), "+f"(d[1]), "+f"(d[2]), "+f"(d[3])
        : "r"(a[0]), "r"(a[1]), "r"(a[2]), "r"(a[3]), "r"(b[0]), "r"(b[1]));
}
__device__ __forceinline__ float tf32r(float x) {
    uint32_t u;
    asm("cvt.rna.tf32.f32 %0, %1;" : "=r"(u) : "f"(x));
    return __uint_as_float(u);
}

// ======================= fp32 -> tf32(rna) round ===========================
__global__ __launch_bounds__(256)
void round_tf32(const float4* __restrict__ in, float4* __restrict__ out, int n4)
{
    int i = blockIdx.x * 256 + threadIdx.x;
    if (i >= n4) return;
    float4 v = in[i];
    float4 r = {tf32r(v.x), tf32r(v.y), tf32r(v.z), tf32r(v.w)};
    out[i] = r;
}

// ======================= single-pass tf32 GEMM =============================
// C[M,N] = A[M,K] * B[N,K]^T, A/B fp32 already tf32-rounded (RNA).
// 128x128 tile, BK=32 floats, 2-stage cp.async, swizzled fp32 smem.
// Fragments loaded via ldmatrix (8x8 fp32 quadrant == 8 rows x 16B).
#define T_STAGE_BYTES 32768
#define T_SMEM_BYTES  (2 * T_STAGE_BYTES)   // 65536

__device__ __forceinline__ void t_load_stage(uint32_t sbase, const float* gA,
                                             const float* gB, int k0, int t)
{
    const float* gs[2] = {gA, gB};
#pragma unroll
    for (int ts = 0; ts < 2; ++ts) {
        const float* g = gs[ts] + k0;
        uint32_t tb = sbase + ts * 16384;
#pragma unroll
        for (int i = 0; i < 4; ++i) {
            int c = t + i * 256;
            int row = c >> 3, cc = c & 7;
            uint32_t off = row * 128 + cc * 16;
            uint32_t sw = off ^ ((off >> 3) & 0x70);
            cp16(tb + sw, g + (size_t)row * K_ + cc * 4);
        }
    }
    cp_commit();
}

__global__ __launch_bounds__(256, 2)
void gemm_tf32(const float* __restrict__ A, const float* __restrict__ B,
               float* __restrict__ C, int N)
{
    extern __shared__ __align__(1024) float smf[];
    const int t    = threadIdx.x;
    const int wid  = t >> 5;
    const int lane = t & 31;
    const int g    = lane >> 2;
    const int c    = lane & 3;
    const int m0w  = (wid >> 2) * 64;
    const int n0w  = (wid & 3) * 32;
    const int rowBase = blockIdx.y << 7;
    const int colBase = blockIdx.x << 7;

    uint32_t sb = s2u(smf);

    // ldmatrix lane geometry (fp32 quadrants, 16B rows)
    const int a_row = (lane & 7) + ((lane >> 3) & 1) * 8;   // A: row within m16
    const int a_cb  = (lane >> 4) * 16;                     // A: k-half byte offset
    const int b_row = (lane & 7) + ((lane >> 4) & 1) * 8;   // B: row within nb-pair (16 rows)
    const int b_cb  = ((lane >> 3) & 1) * 16;               // B: k-half byte offset
    const uint32_t xort = (uint32_t)(lane & 7) << 4;        // swizzle XOR (row&7 == lane&7)

    // per-thread byte bases (within a stage's A / B tile)
    uint32_t abase[4], bbase[2];
#pragma unroll
    for (int mb = 0; mb < 4; ++mb)
        abase[mb] = (uint32_t)(m0w + mb * 16 + a_row) * 128 + a_cb;
#pragma unroll
    for (int nbp = 0; nbp < 2; ++nbp)
        bbase[nbp] = (uint32_t)(n0w + nbp * 16 + b_row) * 128 + b_cb;

    float acc[4][4][4];
#pragma unroll
    for (int mb = 0; mb < 4; ++mb)
#pragma unroll
        for (int nb = 0; nb < 4; ++nb)
#pragma unroll
            for (int r = 0; r < 4; ++r) acc[mb][nb][r] = 0.f;

    const float* gA = A + (size_t)rowBase * K_;
    const float* gB = B + (size_t)colBase * K_;

    const int NT = K_ / 32;   // 64

    t_load_stage(sb, gA, gB, 0, t);
    cp_wait0();
    __syncthreads();

    for (int kt = 0; kt < NT; ++kt) {
        const int s = kt & 1;
        if (kt + 1 < NT)
            t_load_stage(sb + (s ^ 1) * T_STAGE_BYTES, gA, gB, (kt + 1) << 5, t);
        const uint32_t stA = sb + s * T_STAGE_BYTES;
        const uint32_t stB = stA + 16384;

#pragma unroll
        for (int ks = 0; ks < 4; ++ks) {
            const uint32_t ko = (uint32_t)ks * 32;
            uint32_t a[4][4], bfr[4][2];
#pragma unroll
            for (int mb = 0; mb < 4; ++mb)
                ldsm_x4(a[mb], stA + ((abase[mb] + ko) ^ xort));
#pragma unroll
            for (int nbp = 0; nbp < 2; ++nbp) {
                uint32_t r[4];
                ldsm_x4(r, stB + ((bbase[nbp] + ko) ^ xort));
                bfr[2 * nbp][0]     = r[0];
                bfr[2 * nbp][1]     = r[1];
                bfr[2 * nbp + 1][0] = r[2];
                bfr[2 * nbp + 1][1] = r[3];
            }
#pragma unroll
            for (int mb = 0; mb < 4; ++mb)
#pragma unroll
                for (int nb = 0; nb < 4; ++nb)
                    mma_tf32(acc[mb][nb], a[mb], bfr[nb]);
        }
        if (kt + 1 < NT) cp_wait0();
        __syncthreads();
    }

#pragma unroll
    for (int mb = 0; mb < 4; ++mb)
#pragma unroll
        for (int nb = 0; nb < 4; ++nb) {
            int row = rowBase + m0w + mb * 16 + g;
            int col = colBase + n0w + nb * 8 + 2 * c;
            float2 v0 = {acc[mb][nb][0], acc[mb][nb][1]};
            float2 v1 = {acc[mb][nb][2], acc[mb][nb][3]};
            *(float2*)(C + (size_t)row * N + col)       = v0;
            *(float2*)(C + (size_t)(row + 8) * N + col) = v1;
        }
}

// ---------------------------------------------------------------------------
// RoPE + unit-norm + q*attn_scale; tf32-rounded q/k/v in [b,h,s,hd].
// ---------------------------------------------------------------------------
__global__ __launch_bounds__(64)
void rope_norm_kernel(const float* __restrict__ qkv,
                      const float* __restrict__ freqs,
                      const float* __restrict__ scale_p,
                      float* __restrict__ gq, float* __restrict__ gk,
                      float* __restrict__ gv)
{
    const int idx = blockIdx.x;
    const int h = idx % H_;
    const int s = (idx / H_) % S_;
    const int b = idx / (H_ * S_);
    const int i = threadIdx.x;

    const float* base = qkv + (size_t)(b * S_ + s) * NQKV + h * HD_;
    float q0 = base[2 * i],           q1 = base[2 * i + 1];
    float k0 = base[D_ + 2 * i],      k1 = base[D_ + 2 * i + 1];
    float v0 = base[2 * D_ + 2 * i],  v1 = base[2 * D_ + 2 * i + 1];

    float cs = freqs[((size_t)s * 64 + i) * 2 + 0];
    float sn = freqs[((size_t)s * 64 + i) * 2 + 1];

    float qr = q0 * cs - q1 * sn, qi = q0 * sn + q1 * cs;
    float kr = k0 * cs - k1 * sn, ki = k0 * sn + k1 * cs;

    float sq = qr * qr + qi * qi;
    float sk = kr * kr + ki * ki;
#pragma unroll
    for (int off = 16; off > 0; off >>= 1) {
        sq += __shfl_xor_sync(0xffffffffu, sq, off);
        sk += __shfl_xor_sync(0xffffffffu, sk, off);
    }
    __shared__ float smq[2], smk[2];
    if ((i & 31) == 0) { smq[i >> 5] = sq; smk[i >> 5] = sk; }
    __syncthreads();
    float nq = sqrtf(smq[0] + smq[1]) + 1e-6f;
    float nk = sqrtf(smk[0] + smk[1]) + 1e-6f;

    float scl = *scale_p;
    float qs = scl / nq;
    float ks = 1.0f / nk;

    size_t o = ((size_t)(b * H_ + h) * S_ + s) * HD_;
    gq[o + 2 * i] = tf32r(qr * qs);  gq[o + 2 * i + 1] = tf32r(qi * qs);
    gk[o + 2 * i] = tf32r(kr * ks);  gk[o + 2 * i + 1] = tf32r(ki * ks);
    gv[o + 2 * i] = tf32r(v0);       gv[o + 2 * i + 1] = tf32r(v1);
}

// ---------------------------------------------------------------------------
// tf32 flash attention (R8, unchanged). BM=128, BN=64, 256 threads.
// ---------------------------------------------------------------------------
#define QS_OFF 0
#define KS_OFF (128 * 132)
#define KS_BUF (64 * 132)
#define VS_OFF (KS_OFF + 2 * KS_BUF)
#define PS_OFF (VS_OFF + 64 * 136)
#define AT_SMEM_FLOATS (PS_OFF + 128 * 68)
#define AT_SMEM_BYTES (AT_SMEM_FLOATS * 4)    // 204800

__global__ __launch_bounds__(256)
void flash_tc(const float* __restrict__ gq, const float* __restrict__ gk,
              const float* __restrict__ gv, float* __restrict__ gout)
{
    extern __shared__ float sm[];
    uint32_t smb = s2u(sm);
    const int t    = threadIdx.x;
    const int w    = t >> 5;
    const int lane = t & 31;
    const int g    = lane >> 2;
    const int c    = lane & 3;
    const int qt   = (gridDim.x - 1) - blockIdx.x;   // heavy tiles first
    const int bh   = blockIdx.y;
    const int b    = bh >> 4;
    const int h    = bh & 15;
    const int qr0  = w * 16;

    const float* Qg = gq + ((size_t)bh * S_ + qt * 128) * HD_;
    const float* Kg = gk + (size_t)bh * S_ * HD_;
    const float* Vg = gv + (size_t)bh * S_ * HD_;

#pragma unroll
    for (int i = 0; i < 16; ++i) {
        int ci = t + i * 256;
        int row = ci >> 5, cc = ci & 31;
        cp16(smb + (QS_OFF + row * 132 + cc * 4) * 4, Qg + row * HD_ + cc * 4);
    }
    cp_commit();

    const int nkv = 2 * qt + 2;

#pragma unroll
    for (int i = 0; i < 8; ++i) {
        int ci = t + i * 256;
        int row = ci >> 5, cc = ci & 31;
        cp16(smb + (KS_OFF + row * 132 + cc * 4) * 4, Kg + (size_t)row * HD_ + cc * 4);
    }
    cp_commit();
#pragma unroll
    for (int i = 0; i < 8; ++i) {
        int ci = t + i * 256;
        int row = ci >> 5, cc = ci & 31;
        cp16(smb + (VS_OFF + row * 136 + cc * 4) * 4, Vg + (size_t)row * HD_ + cc * 4);
    }
    cp_commit();

    float O[16][4];
#pragma unroll
    for (int nb = 0; nb < 16; ++nb)
#pragma unroll
        for (int r = 0; r < 4; ++r) O[nb][r] = 0.f;
    float m0 = -1e30f, m1 = -1e30f, l0 = 0.f, l1 = 0.f;

    for (int kt = 0; kt < nkv; ++kt) {
        cp_wait1();
        __syncthreads();

        if (kt + 1 < nkv) {
            const float* ksrc = Kg + (size_t)(kt + 1) * 64 * HD_;
            uint32_t kdst = smb + (KS_OFF + ((kt + 1) & 1) * KS_BUF) * 4;
#pragma unroll
            for (int i = 0; i < 8; ++i) {
                int ci = t + i * 256;
                int row = ci >> 5, cc = ci & 31;
                cp16(kdst + (row * 132 + cc * 4) * 4, ksrc + (size_t)row * HD_ + cc * 4);
            }
            cp_commit();
        }

        const int kbase = KS_OFF + (kt & 1) * KS_BUF;
        float sacc[8][4];
#pragma unroll
        for (int nb = 0; nb < 8; ++nb)
#pragma unroll
            for (int r = 0; r < 4; ++r) sacc[nb][r] = 0.f;

#pragma unroll
        for (int ks = 0; ks < 16; ++ks) {
            const int k0 = ks * 8;
            uint32_t a[4];
            a[0] = __float_as_uint(sm[QS_OFF + (qr0 + g) * 132 + k0 + c]);
            a[1] = __float_as_uint(sm[QS_OFF + (qr0 + g + 8) * 132 + k0 + c]);
            a[2] = __float_as_uint(sm[QS_OFF + (qr0 + g) * 132 + k0 + c + 4]);
            a[3] = __float_as_uint(sm[QS_OFF + (qr0 + g + 8) * 132 + k0 + c + 4]);
#pragma unroll
            for (int nb = 0; nb < 8; ++nb) {
                uint32_t bfr[2];
                bfr[0] = __float_as_uint(sm[kbase + (nb * 8 + g) * 132 + k0 + c]);
                bfr[1] = __float_as_uint(sm[kbase + (nb * 8 + g) * 132 + k0 + c + 4]);
                mma_tf32(sacc[nb], a, bfr);
            }
        }

        if (kt >= 2 * qt) {
            int rg0 = qt * 128 + qr0 + g;
#pragma unroll
            for (int nb = 0; nb < 8; ++nb) {
                int col = kt * 64 + nb * 8 + 2 * c;
                if (col     > rg0)     sacc[nb][0] = -1e30f;
                if (col + 1 > rg0)     sacc[nb][1] = -1e30f;
                if (col     > rg0 + 8) sacc[nb][2] = -1e30f;
                if (col + 1 > rg0 + 8) sacc[nb][3] = -1e30f;
            }
        }

        float rm0 = -1e30f, rm1 = -1e30f;
#pragma unroll
        for (int nb = 0; nb < 8; ++nb) {
            rm0 = fmaxf(rm0, fmaxf(sacc[nb][0], sacc[nb][1]));
            rm1 = fmaxf(rm1, fmaxf(sacc[nb][2], sacc[nb][3]));
        }
        rm0 = fmaxf(rm0, __shfl_xor_sync(0xffffffffu, rm0, 1));
        rm0 = fmaxf(rm0, __shfl_xor_sync(0xffffffffu, rm0, 2));
        rm1 = fmaxf(rm1, __shfl_xor_sync(0xffffffffu, rm1, 1));
        rm1 = fmaxf(rm1, __shfl_xor_sync(0xffffffffu, rm1, 2));
        float mn0 = fmaxf(m0, rm0), mn1 = fmaxf(m1, rm1);
        float al0 = __expf(m0 - mn0), al1 = __expf(m1 - mn1);
        float rs0 = 0.f, rs1 = 0.f;
#pragma unroll
        for (int nb = 0; nb < 8; ++nb) {
            sacc[nb][0] = __expf(sacc[nb][0] - mn0);
            sacc[nb][1] = __expf(sacc[nb][1] - mn0);
            sacc[nb][2] = __expf(sacc[nb][2] - mn1);
            sacc[nb][3] = __expf(sacc[nb][3] - mn1);
            rs0 += sacc[nb][0] + sacc[nb][1];
            rs1 += sacc[nb][2] + sacc[nb][3];
        }
        rs0 += __shfl_xor_sync(0xffffffffu, rs0, 1);
        rs0 += __shfl_xor_sync(0xffffffffu, rs0, 2);
        rs1 += __shfl_xor_sync(0xffffffffu, rs1, 1);
        rs1 += __shfl_xor_sync(0xffffffffu, rs1, 2);
        l0 = l0 * al0 + rs0;  m0 = mn0;
        l1 = l1 * al1 + rs1;  m1 = mn1;
#pragma unroll
        for (int nb = 0; nb < 16; ++nb) {
            O[nb][0] *= al0; O[nb][1] *= al0;
            O[nb][2] *= al1; O[nb][3] *= al1;
        }

#pragma unroll
        for (int nb = 0; nb < 8; ++nb) {
            int colp = nb * 8 + 2 * c;
            sm[PS_OFF + (qr0 + g) * 68 + colp]         = tf32r(sacc[nb][0]);
            sm[PS_OFF + (qr0 + g) * 68 + colp + 1]     = tf32r(sacc[nb][1]);
            sm[PS_OFF + (qr0 + g + 8) * 68 + colp]     = tf32r(sacc[nb][2]);
            sm[PS_OFF + (qr0 + g + 8) * 68 + colp + 1] = tf32r(sacc[nb][3]);
        }
        __syncwarp();

        if (kt + 1 < nkv) cp_wait1(); else cp_wait0();
        __syncthreads();

#pragma unroll
        for (int ks = 0; ks < 8; ++ks) {
            const int k0 = ks * 8;
            uint32_t a[4];
            a[0] = __float_as_uint(sm[PS_OFF + (qr0 + g) * 68 + k0 + c]);
            a[1] = __float_as_uint(sm[PS_OFF + (qr0 + g + 8) * 68 + k0 + c]);
            a[2] = __float_as_uint(sm[PS_OFF + (qr0 + g) * 68 + k0 + c + 4]);
            a[3] = __float_as_uint(sm[PS_OFF + (qr0 + g + 8) * 68 + k0 + c + 4]);
#pragma unroll
            for (int nb = 0; nb < 16; ++nb) {
                uint32_t bfr[2];
                bfr[0] = __float_as_uint(sm[VS_OFF + (k0 + c) * 136 + nb * 8 + g]);
                bfr[1] = __float_as_uint(sm[VS_OFF + (k0 + c + 4) * 136 + nb * 8 + g]);
                mma_tf32(O[nb], a, bfr);
            }
        }
        __syncthreads();

        if (kt + 1 < nkv) {
            const float* vsrc = Vg + (size_t)(kt + 1) * 64 * HD_;
#pragma unroll
            for (int i = 0; i < 8; ++i) {
                int ci = t + i * 256;
                int row = ci >> 5, cc = ci & 31;
                cp16(smb + (VS_OFF + row * 136 + cc * 4) * 4,
                     vsrc + (size_t)row * HD_ + cc * 4);
            }
            cp_commit();
        }
    }

    float inv0 = 1.f / l0, inv1 = 1.f / l1;
    int r0 = qt * 128 + qr0 + g;
    int r1 = r0 + 8;
#pragma unroll
    for (int nb = 0; nb < 16; ++nb) {
        int d = nb * 8 + 2 * c;
        float2 v0 = {tf32r(O[nb][0] * inv0), tf32r(O[nb][1] * inv0)};
        float2 v1 = {tf32r(O[nb][2] * inv1), tf32r(O[nb][3] * inv1)};
        *(float2*)(gout + ((size_t)(b * S_ + r0) * H_ + h) * HD_ + d) = v0;
        *(float2*)(gout + ((size_t)(b * S_ + r1) * H_ + h) * HD_ + d) = v1;
    }
}

// ---------------------------------------------------------------------------
extern "C" void kernel_launch(void* const* d_in, const int* in_sizes, int n_in,
                              void* d_out, int out_size)
{
    const float* x      = (const float*)d_in[0];
    const float* freqs  = (const float*)d_in[1];
    const float* wqkv   = (const float*)d_in[2];
    const float* wout   = (const float*)d_in[3];
    const float* ascale = (const float*)d_in[4];
    float* out = (float*)d_out;

    float *qkv, *q, *k, *v, *attn, *wor, *xr, *wqr;
    cudaGetSymbolAddress((void**)&qkv,  g_qkv);
    cudaGetSymbolAddress((void**)&q,    g_q);
    cudaGetSymbolAddress((void**)&k,    g_k);
    cudaGetSymbolAddress((void**)&v,    g_v);
    cudaGetSymbolAddress((void**)&attn, g_attn);
    cudaGetSymbolAddress((void**)&wor,  g_wor);
    cudaGetSymbolAddress((void**)&xr,   g_xr);
    cudaGetSymbolAddress((void**)&wqr,  g_wqr);

    cudaFuncSetAttribute(gemm_tf32, cudaFuncAttributeMaxDynamicSharedMemorySize,
                         T_SMEM_BYTES);
    cudaFuncSetAttribute(flash_tc, cudaFuncAttributeMaxDynamicSharedMemorySize,
                         AT_SMEM_BYTES);

    // 0) tf32(RNA) pre-round all GEMM operands
    {
        int n4 = (M_ * D_) / 4;
        round_tf32<<<(n4 + 255) / 256, 256>>>((const float4*)x, (float4*)xr, n4);
    }
    {
        int n4 = (NQKV * D_) / 4;
        round_tf32<<<(n4 + 255) / 256, 256>>>((const float4*)wqkv, (float4*)wqr, n4);
    }
    {
        int n4 = (D_ * D_) / 4;
        round_tf32<<<(n4 + 255) / 256, 256>>>((const float4*)wout, (float4*)wor, n4);
    }

    // 1) qkv = x @ w_qkv^T  (single-pass tf32, ldmatrix fragments)
    gemm_tf32<<<dim3(NQKV / 128, M_ / 128), 256, T_SMEM_BYTES>>>(xr, wqr, qkv, NQKV);

    // 2) RoPE + norm + scale (tf32-rounded outputs)
    rope_norm_kernel<<<B_ * S_ * H_, 64>>>(qkv, freqs, ascale, q, k, v);

    // 3) flash attention -> tf32-rounded attn [b,s,h,hd]
    flash_tc<<<dim3(S_ / 128, B_ * H_), 256, AT_SMEM_BYTES>>>(q, k, v, attn);

    // 4) out = attn @ w_out^T  (single-pass tf32, ldmatrix fragments)
    gemm_tf32<<<dim3(D_ / 128, M_ / 128), 256, T_SMEM_BYTES>>>(attn, wor, out, D_);
}

// round 12
// speedup vs baseline: 1.2991x; 1.0344x over previous
#include <cuda_runtime.h>
#include <cuda_bf16.h>
#include <math.h>
#include <stdint.h>

// Problem constants
#define B_   2
#define S_   2048
#define D_   2048
#define H_   16
#define HD_  128
#define M_   (B_ * S_)      // 4096
#define NQKV (3 * D_)       // 6144
#define K_   D_             // 2048

// ---------------- scratch (device globals) ---------------------------------
__device__ float g_qkv[(size_t)M_ * NQKV];
__device__ float g_q  [(size_t)M_ * D_];   // [b,h,s,hd], tf32-rounded
__device__ float g_k  [(size_t)M_ * D_];
__device__ float g_v  [(size_t)M_ * D_];
__device__ float g_attn[(size_t)M_ * D_];  // [b,s,h,hd], tf32-rounded
__device__ float g_wor [(size_t)D_ * D_];  // w_out  tf32-rounded
__device__ float g_xr  [(size_t)M_ * D_];  // x      tf32-rounded
__device__ float g_wqr [(size_t)NQKV * D_];// w_qkv  tf32-rounded

// ======================= PTX helpers (compute_103-safe) =====================
__device__ __forceinline__ uint32_t s2u(const void* p) {
    uint32_t a;
    asm("{ .reg .u64 t; cvta.to.shared.u64 t, %1; cvt.u32.u64 %0, t; }"
        : "=r"(a) : "l"(p));
    return a;
}
__device__ __forceinline__ void cp16(uint32_t dst, const void* src) {
    asm volatile("cp.async.ca.shared.global [%0], [%1], 16;" :: "r"(dst), "l"(src));
}
__device__ __forceinline__ void cp_commit() {
    asm volatile("cp.async.commit_group;" ::: "memory");
}
__device__ __forceinline__ void cp_wait0() {
    asm volatile("cp.async.wait_group 0;" ::: "memory");
}
__device__ __forceinline__ void cp_wait1() {
    asm volatile("cp.async.wait_group 1;" ::: "memory");
}
__device__ __forceinline__ void ldsm_x4(uint32_t* r, uint32_t addr) {
    asm volatile("ldmatrix.sync.aligned.m8n8.x4.shared.b16 {%0,%1,%2,%3}, [%4];"
                 : "=r"(r[0]), "=r"(r[1]), "=r"(r[2]), "=r"(r[3]) : "r"(addr));
}
__device__ __forceinline__ void mma_tf32(float* d, const uint32_t* a, const uint32_t* b) {
    asm volatile(
        "mma.sync.aligned.m16n8k8.row.col.f32.tf32.tf32.f32 "
        "{%0,%1,%2,%3}, {%4,%5,%6,%7}, {%8,%9}, {%0,%1,%2,%3};"
        : "+f"(d[0]), "+f"(d[1]), "+f"(d[2]), "+f"(d[3])
        : "r"(a[0]), "r"(a[1]), "r"(a[2]), "r"(a[3]), "r"(b[0]), "r"(b[1]));
}
__device__ __forceinline__ float tf32r(float x) {
    uint32_t u;
    asm("cvt.rna.tf32.f32 %0, %1;" : "=r"(u) : "f"(x));
    return __uint_as_float(u);
}

// ======================= fp32 -> tf32(rna) round ===========================
__global__ __launch_bounds__(256)
void round_tf32(const float4* __restrict__ in, float4* __restrict__ out, int n4)
{
    int i = blockIdx.x * 256 + threadIdx.x;
    if (i >= n4) return;
    float4 v = in[i];
    float4 r = {tf32r(v.x), tf32r(v.y), tf32r(v.z), tf32r(v.w)};
    out[i] = r;
}

// ======================= single-pass tf32 GEMM =============================
// C[M,N] = A[M,K] * B[N,K]^T, A/B fp32 already tf32-rounded (RNA).
// 128x128 CTA tile, 4 warps of 64x64, BK=32, 2-stage cp.async,
// swizzled fp32 smem, ldmatrix fragments. 2 CTAs/SM.
#define T_STAGE_BYTES 32768
#define T_SMEM_BYTES  (2 * T_STAGE_BYTES)   // 65536

__device__ __forceinline__ void t_load_stage(uint32_t sbase, const float* gA,
                                             const float* gB, int k0, int t)
{
    const float* gs[2] = {gA, gB};
#pragma unroll
    for (int ts = 0; ts < 2; ++ts) {
        const float* g = gs[ts] + k0;
        uint32_t tb = sbase + ts * 16384;
#pragma unroll
        for (int i = 0; i < 8; ++i) {
            int c = t + i * 128;              // 0..1023 (128 threads)
            int row = c >> 3, cc = c & 7;
            uint32_t off = row * 128 + cc * 16;
            uint32_t sw = off ^ ((off >> 3) & 0x70);
            cp16(tb + sw, g + (size_t)row * K_ + cc * 4);
        }
    }
    cp_commit();
}

__global__ __launch_bounds__(128, 2)
void gemm_tf32(const float* __restrict__ A, const float* __restrict__ B,
               float* __restrict__ C, int N)
{
    extern __shared__ __align__(1024) float smf[];
    const int t    = threadIdx.x;
    const int wid  = t >> 5;                 // 0..3
    const int lane = t & 31;
    const int g    = lane >> 2;
    const int c    = lane & 3;
    const int m0w  = (wid >> 1) * 64;        // 0 / 64
    const int n0w  = (wid & 1) * 64;         // 0 / 64
    const int rowBase = blockIdx.y << 7;
    const int colBase = blockIdx.x << 7;

    uint32_t sb = s2u(smf);

    // ldmatrix lane geometry (fp32 quadrants, 16B rows)
    const int a_row = (lane & 7) + ((lane >> 3) & 1) * 8;   // A: row within m16
    const int a_cb  = (lane >> 4) * 16;                     // A: k-half byte offset
    const int b_row = (lane & 7) + ((lane >> 4) & 1) * 8;   // B: row within nb-pair
    const int b_cb  = ((lane >> 3) & 1) * 16;               // B: k-half byte offset
    const uint32_t xort = (uint32_t)(lane & 7) << 4;        // swizzle XOR

    uint32_t abase[4], bbase[4];
#pragma unroll
    for (int mb = 0; mb < 4; ++mb)
        abase[mb] = (uint32_t)(m0w + mb * 16 + a_row) * 128 + a_cb;
#pragma unroll
    for (int nbp = 0; nbp < 4; ++nbp)
        bbase[nbp] = (uint32_t)(n0w + nbp * 16 + b_row) * 128 + b_cb;

    float acc[4][8][4];
#pragma unroll
    for (int mb = 0; mb < 4; ++mb)
#pragma unroll
        for (int nb = 0; nb < 8; ++nb)
#pragma unroll
            for (int r = 0; r < 4; ++r) acc[mb][nb][r] = 0.f;

    const float* gA = A + (size_t)rowBase * K_;
    const float* gB = B + (size_t)colBase * K_;

    const int NT = K_ / 32;   // 64

    t_load_stage(sb, gA, gB, 0, t);
    cp_wait0();
    __syncthreads();

    for (int kt = 0; kt < NT; ++kt) {
        const int s = kt & 1;
        if (kt + 1 < NT)
            t_load_stage(sb + (s ^ 1) * T_STAGE_BYTES, gA, gB, (kt + 1) << 5, t);
        const uint32_t stA = sb + s * T_STAGE_BYTES;
        const uint32_t stB = stA + 16384;

#pragma unroll
        for (int ks = 0; ks < 4; ++ks) {
            const uint32_t ko = (uint32_t)ks * 32;
            uint32_t a[4][4], bfr[8][2];
#pragma unroll
            for (int mb = 0; mb < 4; ++mb)
                ldsm_x4(a[mb], stA + ((abase[mb] + ko) ^ xort));
#pragma unroll
            for (int nbp = 0; nbp < 4; ++nbp) {
                uint32_t r[4];
                ldsm_x4(r, stB + ((bbase[nbp] + ko) ^ xort));
                bfr[2 * nbp][0]     = r[0];
                bfr[2 * nbp][1]     = r[1];
                bfr[2 * nbp + 1][0] = r[2];
                bfr[2 * nbp + 1][1] = r[3];
            }
#pragma unroll
            for (int mb = 0; mb < 4; ++mb)
#pragma unroll
                for (int nb = 0; nb < 8; ++nb)
                    mma_tf32(acc[mb][nb], a[mb], bfr[nb]);
        }
        if (kt + 1 < NT) cp_wait0();
        __syncthreads();
    }

#pragma unroll
    for (int mb = 0; mb < 4; ++mb)
#pragma unroll
        for (int nb = 0; nb < 8; ++nb) {
            int row = rowBase + m0w + mb * 16 + g;
            int col = colBase + n0w + nb * 8 + 2 * c;
            float2 v0 = {acc[mb][nb][0], acc[mb][nb][1]};
            float2 v1 = {acc[mb][nb][2], acc[mb][nb][3]};
            *(float2*)(C + (size_t)row * N + col)       = v0;
            *(float2*)(C + (size_t)(row + 8) * N + col) = v1;
        }
}

// ---------------------------------------------------------------------------
// RoPE + unit-norm + q*attn_scale; tf32-rounded q/k/v in [b,h,s,hd].
// ---------------------------------------------------------------------------
__global__ __launch_bounds__(64)
void rope_norm_kernel(const float* __restrict__ qkv,
                      const float* __restrict__ freqs,
                      const float* __restrict__ scale_p,
                      float* __restrict__ gq, float* __restrict__ gk,
                      float* __restrict__ gv)
{
    const int idx = blockIdx.x;
    const int h = idx % H_;
    const int s = (idx / H_) % S_;
    const int b = idx / (H_ * S_);
    const int i = threadIdx.x;

    const float* base = qkv + (size_t)(b * S_ + s) * NQKV + h * HD_;
    float q0 = base[2 * i],           q1 = base[2 * i + 1];
    float k0 = base[D_ + 2 * i],      k1 = base[D_ + 2 * i + 1];
    float v0 = base[2 * D_ + 2 * i],  v1 = base[2 * D_ + 2 * i + 1];

    float cs = freqs[((size_t)s * 64 + i) * 2 + 0];
    float sn = freqs[((size_t)s * 64 + i) * 2 + 1];

    float qr = q0 * cs - q1 * sn, qi = q0 * sn + q1 * cs;
    float kr = k0 * cs - k1 * sn, ki = k0 * sn + k1 * cs;

    float sq = qr * qr + qi * qi;
    float sk = kr * kr + ki * ki;
#pragma unroll
    for (int off = 16; off > 0; off >>= 1) {
        sq += __shfl_xor_sync(0xffffffffu, sq, off);
        sk += __shfl_xor_sync(0xffffffffu, sk, off);
    }
    __shared__ float smq[2], smk[2];
    if ((i & 31) == 0) { smq[i >> 5] = sq; smk[i >> 5] = sk; }
    __syncthreads();
    float nq = sqrtf(smq[0] + smq[1]) + 1e-6f;
    float nk = sqrtf(smk[0] + smk[1]) + 1e-6f;

    float scl = *scale_p;
    float qs = scl / nq;
    float ks = 1.0f / nk;

    size_t o = ((size_t)(b * H_ + h) * S_ + s) * HD_;
    gq[o + 2 * i] = tf32r(qr * qs);  gq[o + 2 * i + 1] = tf32r(qi * qs);
    gk[o + 2 * i] = tf32r(kr * ks);  gk[o + 2 * i + 1] = tf32r(ki * ks);
    gv[o + 2 * i] = tf32r(v0);       gv[o + 2 * i + 1] = tf32r(v1);
}

// ---------------------------------------------------------------------------
// tf32 flash attention (R8, unchanged). BM=128, BN=64, 256 threads.
// ---------------------------------------------------------------------------
#define QS_OFF 0
#define KS_OFF (128 * 132)
#define KS_BUF (64 * 132)
#define VS_OFF (KS_OFF + 2 * KS_BUF)
#define PS_OFF (VS_OFF + 64 * 136)
#define AT_SMEM_FLOATS (PS_OFF + 128 * 68)
#define AT_SMEM_BYTES (AT_SMEM_FLOATS * 4)    // 204800

__global__ __launch_bounds__(256)
void flash_tc(const float* __restrict__ gq, const float* __restrict__ gk,
              const float* __restrict__ gv, float* __restrict__ gout)
{
    extern __shared__ float sm[];
    uint32_t smb = s2u(sm);
    const int t    = threadIdx.x;
    const int w    = t >> 5;
    const int lane = t & 31;
    const int g    = lane >> 2;
    const int c    = lane & 3;
    const int qt   = (gridDim.x - 1) - blockIdx.x;   // heavy tiles first
    const int bh   = blockIdx.y;
    const int b    = bh >> 4;
    const int h    = bh & 15;
    const int qr0  = w * 16;

    const float* Qg = gq + ((size_t)bh * S_ + qt * 128) * HD_;
    const float* Kg = gk + (size_t)bh * S_ * HD_;
    const float* Vg = gv + (size_t)bh * S_ * HD_;

#pragma unroll
    for (int i = 0; i < 16; ++i) {
        int ci = t + i * 256;
        int row = ci >> 5, cc = ci & 31;
        cp16(smb + (QS_OFF + row * 132 + cc * 4) * 4, Qg + row * HD_ + cc * 4);
    }
    cp_commit();

    const int nkv = 2 * qt + 2;

#pragma unroll
    for (int i = 0; i < 8; ++i) {
        int ci = t + i * 256;
        int row = ci >> 5, cc = ci & 31;
        cp16(smb + (KS_OFF + row * 132 + cc * 4) * 4, Kg + (size_t)row * HD_ + cc * 4);
    }
    cp_commit();
#pragma unroll
    for (int i = 0; i < 8; ++i) {
        int ci = t + i * 256;
        int row = ci >> 5, cc = ci & 31;
        cp16(smb + (VS_OFF + row * 136 + cc * 4) * 4, Vg + (size_t)row * HD_ + cc * 4);
    }
    cp_commit();

    float O[16][4];
#pragma unroll
    for (int nb = 0; nb < 16; ++nb)
#pragma unroll
        for (int r = 0; r < 4; ++r) O[nb][r] = 0.f;
    float m0 = -1e30f, m1 = -1e30f, l0 = 0.f, l1 = 0.f;

    for (int kt = 0; kt < nkv; ++kt) {
        cp_wait1();
        __syncthreads();

        if (kt + 1 < nkv) {
            const float* ksrc = Kg + (size_t)(kt + 1) * 64 * HD_;
            uint32_t kdst = smb + (KS_OFF + ((kt + 1) & 1) * KS_BUF) * 4;
#pragma unroll
            for (int i = 0; i < 8; ++i) {
                int ci = t + i * 256;
                int row = ci >> 5, cc = ci & 31;
                cp16(kdst + (row * 132 + cc * 4) * 4, ksrc + (size_t)row * HD_ + cc * 4);
            }
            cp_commit();
        }

        const int kbase = KS_OFF + (kt & 1) * KS_BUF;
        float sacc[8][4];
#pragma unroll
        for (int nb = 0; nb < 8; ++nb)
#pragma unroll
            for (int r = 0; r < 4; ++r) sacc[nb][r] = 0.f;

#pragma unroll
        for (int ks = 0; ks < 16; ++ks) {
            const int k0 = ks * 8;
            uint32_t a[4];
            a[0] = __float_as_uint(sm[QS_OFF + (qr0 + g) * 132 + k0 + c]);
            a[1] = __float_as_uint(sm[QS_OFF + (qr0 + g + 8) * 132 + k0 + c]);
            a[2] = __float_as_uint(sm[QS_OFF + (qr0 + g) * 132 + k0 + c + 4]);
            a[3] = __float_as_uint(sm[QS_OFF + (qr0 + g + 8) * 132 + k0 + c + 4]);
#pragma unroll
            for (int nb = 0; nb < 8; ++nb) {
                uint32_t bfr[2];
                bfr[0] = __float_as_uint(sm[kbase + (nb * 8 + g) * 132 + k0 + c]);
                bfr[1] = __float_as_uint(sm[kbase + (nb * 8 + g) * 132 + k0 + c + 4]);
                mma_tf32(sacc[nb], a, bfr);
            }
        }

        if (kt >= 2 * qt) {
            int rg0 = qt * 128 + qr0 + g;
#pragma unroll
            for (int nb = 0; nb < 8; ++nb) {
                int col = kt * 64 + nb * 8 + 2 * c;
                if (col     > rg0)     sacc[nb][0] = -1e30f;
                if (col + 1 > rg0)     sacc[nb][1] = -1e30f;
                if (col     > rg0 + 8) sacc[nb][2] = -1e30f;
                if (col + 1 > rg0 + 8) sacc[nb][3] = -1e30f;
            }
        }

        float rm0 = -1e30f, rm1 = -1e30f;
#pragma unroll
        for (int nb = 0; nb < 8; ++nb) {
            rm0 = fmaxf(rm0, fmaxf(sacc[nb][0], sacc[nb][1]));
            rm1 = fmaxf(rm1, fmaxf(sacc[nb][2], sacc[nb][3]));
        }
        rm0 = fmaxf(rm0, __shfl_xor_sync(0xffffffffu, rm0, 1));
        rm0 = fmaxf(rm0, __shfl_xor_sync(0xffffffffu, rm0, 2));
        rm1 = fmaxf(rm1, __shfl_xor_sync(0xffffffffu, rm1, 1));
        rm1 = fmaxf(rm1, __shfl_xor_sync(0xffffffffu, rm1, 2));
        float mn0 = fmaxf(m0, rm0), mn1 = fmaxf(m1, rm1);
        float al0 = __expf(m0 - mn0), al1 = __expf(m1 - mn1);
        float rs0 = 0.f, rs1 = 0.f;
#pragma unroll
        for (int nb = 0; nb < 8; ++nb) {
            sacc[nb][0] = __expf(sacc[nb][0] - mn0);
            sacc[nb][1] = __expf(sacc[nb][1] - mn0);
            sacc[nb][2] = __expf(sacc[nb][2] - mn1);
            sacc[nb][3] = __expf(sacc[nb][3] - mn1);
            rs0 += sacc[nb][0] + sacc[nb][1];
            rs1 += sacc[nb][2] + sacc[nb][3];
        }
        rs0 += __shfl_xor_sync(0xffffffffu, rs0, 1);
        rs0 += __shfl_xor_sync(0xffffffffu, rs0, 2);
        rs1 += __shfl_xor_sync(0xffffffffu, rs1, 1);
        rs1 += __shfl_xor_sync(0xffffffffu, rs1, 2);
        l0 = l0 * al0 + rs0;  m0 = mn0;
        l1 = l1 * al1 + rs1;  m1 = mn1;
#pragma unroll
        for (int nb = 0; nb < 16; ++nb) {
            O[nb][0] *= al0; O[nb][1] *= al0;
            O[nb][2] *= al1; O[nb][3] *= al1;
        }

#pragma unroll
        for (int nb = 0; nb < 8; ++nb) {
            int colp = nb * 8 + 2 * c;
            sm[PS_OFF + (qr0 + g) * 68 + colp]         = tf32r(sacc[nb][0]);
            sm[PS_OFF + (qr0 + g) * 68 + colp + 1]     = tf32r(sacc[nb][1]);
            sm[PS_OFF + (qr0 + g + 8) * 68 + colp]     = tf32r(sacc[nb][2]);
            sm[PS_OFF + (qr0 + g + 8) * 68 + colp + 1] = tf32r(sacc[nb][3]);
        }
        __syncwarp();

        if (kt + 1 < nkv) cp_wait1(); else cp_wait0();
        __syncthreads();

#pragma unroll
        for (int ks = 0; ks < 8; ++ks) {
            const int k0 = ks * 8;
            uint32_t a[4];
            a[0] = __float_as_uint(sm[PS_OFF + (qr0 + g) * 68 + k0 + c]);
            a[1] = __float_as_uint(sm[PS_OFF + (qr0 + g + 8) * 68 + k0 + c]);
            a[2] = __float_as_uint(sm[PS_OFF + (qr0 + g) * 68 + k0 + c + 4]);
            a[3] = __float_as_uint(sm[PS_OFF + (qr0 + g + 8) * 68 + k0 + c + 4]);
#pragma unroll
            for (int nb = 0; nb < 16; ++nb) {
                uint32_t bfr[2];
                bfr[0] = __float_as_uint(sm[VS_OFF + (k0 + c) * 136 + nb * 8 + g]);
                bfr[1] = __float_as_uint(sm[VS_OFF + (k0 + c + 4) * 136 + nb * 8 + g]);
                mma_tf32(O[nb], a, bfr);
            }
        }
        __syncthreads();

        if (kt + 1 < nkv) {
            const float* vsrc = Vg + (size_t)(kt + 1) * 64 * HD_;
#pragma unroll
            for (int i = 0; i < 8; ++i) {
                int ci = t + i * 256;
                int row = ci >> 5, cc = ci & 31;
                cp16(smb + (VS_OFF + row * 136 + cc * 4) * 4,
                     vsrc + (size_t)row * HD_ + cc * 4);
            }
            cp_commit();
        }
    }

    float inv0 = 1.f / l0, inv1 = 1.f / l1;
    int r0 = qt * 128 + qr0 + g;
    int r1 = r0 + 8;
#pragma unroll
    for (int nb = 0; nb < 16; ++nb) {
        int d = nb * 8 + 2 * c;
        float2 v0 = {tf32r(O[nb][0] * inv0), tf32r(O[nb][1] * inv0)};
        float2 v1 = {tf32r(O[nb][2] * inv1), tf32r(O[nb][3] * inv1)};
        *(float2*)(gout + ((size_t)(b * S_ + r0) * H_ + h) * HD_ + d) = v0;
        *(float2*)(gout + ((size_t)(b * S_ + r1) * H_ + h) * HD_ + d) = v1;
    }
}

// ---------------------------------------------------------------------------
extern "C" void kernel_launch(void* const* d_in, const int* in_sizes, int n_in,
                              void* d_out, int out_size)
{
    const float* x      = (const float*)d_in[0];
    const float* freqs  = (const float*)d_in[1];
    const float* wqkv   = (const float*)d_in[2];
    const float* wout   = (const float*)d_in[3];
    const float* ascale = (const float*)d_in[4];
    float* out = (float*)d_out;

    float *qkv, *q, *k, *v, *attn, *wor, *xr, *wqr;
    cudaGetSymbolAddress((void**)&qkv,  g_qkv);
    cudaGetSymbolAddress((void**)&q,    g_q);
    cudaGetSymbolAddress((void**)&k,    g_k);
    cudaGetSymbolAddress((void**)&v,    g_v);
    cudaGetSymbolAddress((void**)&attn, g_attn);
    cudaGetSymbolAddress((void**)&wor,  g_wor);
    cudaGetSymbolAddress((void**)&xr,   g_xr);
    cudaGetSymbolAddress((void**)&wqr,  g_wqr);

    cudaFuncSetAttribute(gemm_tf32, cudaFuncAttributeMaxDynamicSharedMemorySize,
                         T_SMEM_BYTES);
    cudaFuncSetAttribute(flash_tc, cudaFuncAttributeMaxDynamicSharedMemorySize,
                         AT_SMEM_BYTES);

    // 0) tf32(RNA) pre-round all GEMM operands
    {
        int n4 = (M_ * D_) / 4;
        round_tf32<<<(n4 + 255) / 256, 256>>>((const float4*)x, (float4*)xr, n4);
    }
    {
        int n4 = (NQKV * D_) / 4;
        round_tf32<<<(n4 + 255) / 256, 256>>>((const float4*)wqkv, (float4*)wqr, n4);
    }
    {
        int n4 = (D_ * D_) / 4;
        round_tf32<<<(n4 + 255) / 256, 256>>>((const float4*)wout, (float4*)wor, n4);
    }

    // 1) qkv = x @ w_qkv^T  (tf32, 4 warps x 64x64)
    gemm_tf32<<<dim3(NQKV / 128, M_ / 128), 128, T_SMEM_BYTES>>>(xr, wqr, qkv, NQKV);

    // 2) RoPE + norm + scale (tf32-rounded outputs)
    rope_norm_kernel<<<B_ * S_ * H_, 64>>>(qkv, freqs, ascale, q, k, v);

    // 3) flash attention -> tf32-rounded attn [b,s,h,hd]
    flash_tc<<<dim3(S_ / 128, B_ * H_), 256, AT_SMEM_BYTES>>>(q, k, v, attn);

    // 4) out = attn @ w_out^T  (tf32, 4 warps x 64x64)
    gemm_tf32<<<dim3(D_ / 128, M_ / 128), 128, T_SMEM_BYTES>>>(attn, wor, out, D_);
}